// round 7
// baseline (speedup 1.0000x reference)
#include <cuda_runtime.h>
#include <cuda_bf16.h>
#include <math.h>

#define QLEN 1024
#define BSZ 4
#define DM 1024
#define NH 16
#define DH 64
#define HD (NH*DH)          /* 1024 */
#define ROWS (QLEN*BSZ)     /* 4096 */

// ---------------- scratch (device globals; no allocation allowed) ----------
__device__ __align__(16) float g_heads[ROWS * 3 * HD];
__device__ __align__(16) float g_rk[QLEN * HD];
__device__ __align__(16) float g_vec[ROWS * HD];
__device__ __align__(16) float g_ao[ROWS * DM];

// preconverted bf16 hi/lo operands
__device__ __align__(16) __nv_bfloat16 g_w_h[ROWS * DM],    g_w_l[ROWS * DM];
__device__ __align__(16) __nv_bfloat16 g_vec_h[ROWS * HD],  g_vec_l[ROWS * HD];
__device__ __align__(16) __nv_bfloat16 g_r_h[QLEN * DM],    g_r_l[QLEN * DM];
__device__ __align__(16) __nv_bfloat16 g_qkvT_h[3*HD * DM], g_qkvT_l[3*HD * DM]; // [n][k]
__device__ __align__(16) __nv_bfloat16 g_wrT_h[HD * DM],    g_wrT_l[HD * DM];
__device__ __align__(16) __nv_bfloat16 g_woT_h[DM * HD],    g_woT_l[DM * HD];

// ============================================================================
// helpers
// ============================================================================
__device__ __forceinline__ void mma16816(float* c, const unsigned* a, const unsigned* b)
{
    asm volatile(
        "mma.sync.aligned.m16n8k16.row.col.f32.bf16.bf16.f32 "
        "{%0,%1,%2,%3}, {%4,%5,%6,%7}, {%8,%9}, {%0,%1,%2,%3};\n"
        : "+f"(c[0]), "+f"(c[1]), "+f"(c[2]), "+f"(c[3])
        : "r"(a[0]), "r"(a[1]), "r"(a[2]), "r"(a[3]), "r"(b[0]), "r"(b[1]));
}

__device__ __forceinline__ unsigned pack_bf2(__nv_bfloat16 a, __nv_bfloat16 b)
{
    return ((unsigned)__bfloat16_as_ushort(b) << 16) | __bfloat16_as_ushort(a);
}

__device__ __forceinline__ void cp16(unsigned dst, const void* src)
{
    asm volatile("cp.async.cg.shared.global [%0], [%1], 16;\n" :: "r"(dst), "l"(src));
}

// ---------------- convert fp32 -> bf16 hi/lo (row-major passthrough) --------
__global__ __launch_bounds__(256) void conv_split(
    const float* __restrict__ X, __nv_bfloat16* __restrict__ Xh,
    __nv_bfloat16* __restrict__ Xl, int total)
{
    int i = (blockIdx.x * 256 + threadIdx.x) * 4;
    if (i >= total) return;
    float4 v = *(const float4*)&X[i];
    __nv_bfloat16 h0 = __float2bfloat16(v.x);
    __nv_bfloat16 h1 = __float2bfloat16(v.y);
    __nv_bfloat16 h2 = __float2bfloat16(v.z);
    __nv_bfloat16 h3 = __float2bfloat16(v.w);
    uint2 ph = make_uint2(pack_bf2(h0, h1), pack_bf2(h2, h3));
    uint2 pl = make_uint2(
        pack_bf2(__float2bfloat16(v.x - __bfloat162float(h0)),
                 __float2bfloat16(v.y - __bfloat162float(h1))),
        pack_bf2(__float2bfloat16(v.z - __bfloat162float(h2)),
                 __float2bfloat16(v.w - __bfloat162float(h3))));
    *(uint2*)&Xh[i] = ph;
    *(uint2*)&Xl[i] = pl;
}

// ---------------- convert + transpose: B[K][N] -> Bt[N][K] hi/lo -----------
__global__ __launch_bounds__(256) void conv_split_T(
    const float* __restrict__ B, __nv_bfloat16* __restrict__ Bth,
    __nv_bfloat16* __restrict__ Btl, int K, int N)
{
    __shared__ float tile[32][33];
    int k0 = blockIdx.y * 32, n0 = blockIdx.x * 32;
    int tx = threadIdx.x & 31, ty = threadIdx.x >> 5;
#pragma unroll
    for (int i = 0; i < 4; i++) {
        int k = ty + i * 8;
        tile[k][tx] = B[(size_t)(k0 + k) * N + n0 + tx];
    }
    __syncthreads();
#pragma unroll
    for (int i = 0; i < 4; i++) {
        int n = ty + i * 8;
        float v = tile[tx][n];
        __nv_bfloat16 h = __float2bfloat16(v);
        Bth[(size_t)(n0 + n) * K + k0 + tx] = h;
        Btl[(size_t)(n0 + n) * K + k0 + tx] = __float2bfloat16(v - __bfloat162float(h));
    }
}

// ============================================================================
// Pipelined bf16 GEMM: C[M][N] = A[M][K] @ Bt[N][K]^T, hi/lo split (3 MMAs).
// 128x128x32 tile, 256 threads, 4-stage cp.async pipeline.
// ============================================================================
#define APAD 40
#define TILE_E (128*APAD)      /* bf16 elems per tile buffer */
#define STAGES 4
#define GEMM_SMEM (STAGES * 4 * TILE_E * 2)   /* 163840 bytes */

__global__ __launch_bounds__(256) void gemm_bf16(
    const __nv_bfloat16* __restrict__ Ah, const __nv_bfloat16* __restrict__ Al,
    const __nv_bfloat16* __restrict__ Bh, const __nv_bfloat16* __restrict__ Bl,
    float* __restrict__ C, int M, int N, int K)
{
    extern __shared__ __nv_bfloat16 smem[];
    const unsigned smem_base = (unsigned)__cvta_generic_to_shared(smem);

    const int tid  = threadIdx.x;
    const int row0 = blockIdx.y * 128;
    const int col0 = blockIdx.x * 128;
    const int warp = tid >> 5, lane = tid & 31;
    const int wm = warp & 1;
    const int wn = warp >> 1;
    const int g  = lane >> 2;
    const int tg = lane & 3;

    float acc[4][4][4];
#pragma unroll
    for (int mf = 0; mf < 4; mf++)
#pragma unroll
        for (int nf = 0; nf < 4; nf++)
#pragma unroll
            for (int i = 0; i < 4; i++) acc[mf][nf][i] = 0.f;

    // fill one pipeline stage: 4 tiles (Ah,Al,Bh,Bl), 512 x 16B chunks each
    auto fill_stage = [&](int k0, int s) {
        unsigned sb = smem_base + (unsigned)(s * 4 * TILE_E) * 2u;
#pragma unroll
        for (int i = 0; i < 2; i++) {
            int idx = tid + i * 256;          // 0..511
            int rr = idx >> 2;                // 0..127
            int cc = (idx & 3) * 8;           // bf16 offset
            unsigned off = (unsigned)(rr * APAD + cc) * 2u;
            size_t ga = (size_t)(row0 + rr) * K + k0 + cc;
            size_t gb = (size_t)(col0 + rr) * K + k0 + cc;
            cp16(sb + off,                  Ah + ga);
            cp16(sb + TILE_E*2 + off,       Al + ga);
            cp16(sb + 2*TILE_E*2 + off,     Bh + gb);
            cp16(sb + 3*TILE_E*2 + off,     Bl + gb);
        }
    };

    const int nk = K / 32;
#pragma unroll
    for (int s = 0; s < STAGES - 1; s++) {
        fill_stage(s * 32, s);
        asm volatile("cp.async.commit_group;\n");
    }

    for (int it = 0; it < nk; it++) {
        asm volatile("cp.async.wait_group %0;\n" :: "n"(STAGES - 2));
        __syncthreads();

        const int s = it % STAGES;
        const __nv_bfloat16* cAh = smem + s * 4 * TILE_E;
        const __nv_bfloat16* cAl = cAh + TILE_E;
        const __nv_bfloat16* cBh = cAl + TILE_E;
        const __nv_bfloat16* cBl = cBh + TILE_E;

#pragma unroll
        for (int ks = 0; ks < 2; ks++) {
            int kb = ks * 16 + tg * 2;

            unsigned bh[4][2], bl[4][2];
#pragma unroll
            for (int nf = 0; nf < 4; nf++) {
                int n = wn * 32 + nf * 8 + g;
                bh[nf][0] = *(unsigned*)&cBh[n * APAD + kb];
                bh[nf][1] = *(unsigned*)&cBh[n * APAD + kb + 8];
                bl[nf][0] = *(unsigned*)&cBl[n * APAD + kb];
                bl[nf][1] = *(unsigned*)&cBl[n * APAD + kb + 8];
            }
#pragma unroll
            for (int mf = 0; mf < 4; mf++) {
                int r = wm * 64 + mf * 16 + g;
                unsigned ah[4], al[4];
                ah[0] = *(unsigned*)&cAh[r * APAD + kb];
                ah[1] = *(unsigned*)&cAh[(r + 8) * APAD + kb];
                ah[2] = *(unsigned*)&cAh[r * APAD + kb + 8];
                ah[3] = *(unsigned*)&cAh[(r + 8) * APAD + kb + 8];
                al[0] = *(unsigned*)&cAl[r * APAD + kb];
                al[1] = *(unsigned*)&cAl[(r + 8) * APAD + kb];
                al[2] = *(unsigned*)&cAl[r * APAD + kb + 8];
                al[3] = *(unsigned*)&cAl[(r + 8) * APAD + kb + 8];
#pragma unroll
                for (int nf = 0; nf < 4; nf++) {
                    mma16816(acc[mf][nf], ah, bh[nf]);
                    mma16816(acc[mf][nf], ah, bl[nf]);
                    mma16816(acc[mf][nf], al, bh[nf]);
                }
            }
        }
        __syncthreads();

        int kpre = (it + STAGES - 1) * 32;
        if (kpre < K) fill_stage(kpre, (it + STAGES - 1) % STAGES);
        asm volatile("cp.async.commit_group;\n");
    }

#pragma unroll
    for (int mf = 0; mf < 4; mf++) {
        int r = row0 + wm * 64 + mf * 16 + g;
#pragma unroll
        for (int nf = 0; nf < 4; nf++) {
            int c = col0 + wn * 32 + nf * 8 + tg * 2;
            *(float2*)&C[(size_t)r * N + c]       = make_float2(acc[mf][nf][0], acc[mf][nf][1]);
            *(float2*)&C[(size_t)(r + 8) * N + c] = make_float2(acc[mf][nf][2], acc[mf][nf][3]);
        }
    }
}

// ============================================================================
// Tensor-core fused rel-attention (unchanged from R6 passing version)
// ============================================================================
#define ROWP 72
#define TBYTES (64*ROWP*2)
#define OFF_UNION (10*TBYTES)
#define GSTR 133
#define OFF_MISC (OFF_UNION + 64*GSTR*4)
#define ATTN_SMEM (OFF_MISC + 3*256 + 2*512)

__global__ __launch_bounds__(256) void attn_mma(
    const float* __restrict__ heads, const float* __restrict__ rk,
    const float* __restrict__ rwb, const float* __restrict__ rrb,
    float* __restrict__ vec)
{
    extern __shared__ char smc[];
    __nv_bfloat16* qw_h = (__nv_bfloat16*)(smc);
    __nv_bfloat16* qw_l = (__nv_bfloat16*)(smc + 1*TBYTES);
    __nv_bfloat16* qr_h = (__nv_bfloat16*)(smc + 2*TBYTES);
    __nv_bfloat16* qr_l = (__nv_bfloat16*)(smc + 3*TBYTES);
    __nv_bfloat16* kk_h = (__nv_bfloat16*)(smc + 4*TBYTES);
    __nv_bfloat16* kk_l = (__nv_bfloat16*)(smc + 5*TBYTES);
    __nv_bfloat16* vt_h = (__nv_bfloat16*)(smc + 6*TBYTES);
    __nv_bfloat16* vt_l = (__nv_bfloat16*)(smc + 7*TBYTES);
    __nv_bfloat16* bd_h = (__nv_bfloat16*)(smc + 8*TBYTES);
    __nv_bfloat16* bd_l = (__nv_bfloat16*)(smc + 9*TBYTES);
    __nv_bfloat16* pp_h = (__nv_bfloat16*)(smc + OFF_UNION);
    __nv_bfloat16* pp_l = (__nv_bfloat16*)(smc + OFF_UNION + TBYTES);
    float* G      = (float*)(smc + OFF_UNION);
    float* m_s    = (float*)(smc + OFF_MISC);
    float* l_s    = (float*)(smc + OFF_MISC + 256);
    float* corr_s = (float*)(smc + OFF_MISC + 512);
    float* pmax   = (float*)(smc + OFF_MISC + 768);
    float* psum   = (float*)(smc + OFF_MISC + 1280);

    const int tid = threadIdx.x;
    const int warp = tid >> 5, lane = tid & 31;
    const int g = lane >> 2, tg = lane & 3;
    const int mrow = (warp & 3) * 16;
    const int ncol = (warp >> 2) * 32;
    const int wn = warp >> 2;
    const int i0 = blockIdx.x * 64;
    const int n  = blockIdx.y;
    const int b  = blockIdx.z;
    const int r0 = mrow + g, r1 = r0 + 8;

    for (int idx = tid; idx < 4096; idx += 256) {
        int r = idx >> 6, d = idx & 63;
        float v = heads[(size_t)((i0 + r) * BSZ + b) * 3072 + n * 64 + d];
        float vw = v + rwb[n * 64 + d];
        float vr = v + rrb[n * 64 + d];
        __nv_bfloat16 h = __float2bfloat16(vw);
        qw_h[r * ROWP + d] = h;
        qw_l[r * ROWP + d] = __float2bfloat16(vw - __bfloat162float(h));
        h = __float2bfloat16(vr);
        qr_h[r * ROWP + d] = h;
        qr_l[r * ROWP + d] = __float2bfloat16(vr - __bfloat162float(h));
    }
    if (tid < 64) { m_s[tid] = -3.0e38f; l_s[tid] = 0.f; }

    float acc[4][4];
#pragma unroll
    for (int nf = 0; nf < 4; nf++)
#pragma unroll
        for (int i = 0; i < 4; i++) acc[nf][i] = 0.f;

    const float scale = 0.125f;
    const int ntiles = blockIdx.x + 1;

    for (int jt = 0; jt < ntiles; ++jt) {
        const int j0 = jt * 64;
        const int base = 960 - i0 + j0;
        __syncthreads();

        for (int idx = tid; idx < 4096; idx += 256) {
            int c = idx >> 6, d = idx & 63;
            size_t off = (size_t)((j0 + c) * BSZ + b) * 3072 + n * 64 + d;
            float kv = heads[off + 1024];
            float vv = heads[off + 2048];
            __nv_bfloat16 h = __float2bfloat16(kv);
            kk_h[c * ROWP + d] = h;
            kk_l[c * ROWP + d] = __float2bfloat16(kv - __bfloat162float(h));
            h = __float2bfloat16(vv);
            vt_h[d * ROWP + c] = h;
            vt_l[d * ROWP + c] = __float2bfloat16(vv - __bfloat162float(h));
        }
        for (int idx = tid; idx < 4096; idx += 256) {
            int t = idx >> 6, d = idx & 63;
            float bv = rk[(size_t)(base + t) * HD + n * 64 + d];
            __nv_bfloat16 h = __float2bfloat16(bv);
            bd_h[t * ROWP + d] = h;
            bd_l[t * ROWP + d] = __float2bfloat16(bv - __bfloat162float(h));
        }
        __syncthreads();

        {
            float gacc[4][4];
#pragma unroll
            for (int nf = 0; nf < 4; nf++)
#pragma unroll
                for (int i = 0; i < 4; i++) gacc[nf][i] = 0.f;
#pragma unroll
            for (int ks = 0; ks < 4; ks++) {
                int kb = ks * 16 + tg * 2;
                unsigned ah[4], al[4];
                ah[0] = *(unsigned*)&qr_h[r0 * ROWP + kb];
                ah[1] = *(unsigned*)&qr_h[r1 * ROWP + kb];
                ah[2] = *(unsigned*)&qr_h[r0 * ROWP + kb + 8];
                ah[3] = *(unsigned*)&qr_h[r1 * ROWP + kb + 8];
                al[0] = *(unsigned*)&qr_l[r0 * ROWP + kb];
                al[1] = *(unsigned*)&qr_l[r1 * ROWP + kb];
                al[2] = *(unsigned*)&qr_l[r0 * ROWP + kb + 8];
                al[3] = *(unsigned*)&qr_l[r1 * ROWP + kb + 8];
#pragma unroll
                for (int nf = 0; nf < 4; nf++) {
                    int nn = ncol + nf * 8 + g;
                    unsigned bh[2], bl[2];
                    bh[0] = *(unsigned*)&bd_h[nn * ROWP + kb];
                    bh[1] = *(unsigned*)&bd_h[nn * ROWP + kb + 8];
                    bl[0] = *(unsigned*)&bd_l[nn * ROWP + kb];
                    bl[1] = *(unsigned*)&bd_l[nn * ROWP + kb + 8];
                    mma16816(gacc[nf], ah, bh);
                    mma16816(gacc[nf], ah, bl);
                    mma16816(gacc[nf], al, bh);
                }
            }
#pragma unroll
            for (int nf = 0; nf < 4; nf++) {
                int col = ncol + nf * 8 + tg * 2;
                G[r0 * GSTR + col]     = gacc[nf][0];
                G[r0 * GSTR + col + 1] = gacc[nf][1];
                G[r1 * GSTR + col]     = gacc[nf][2];
                G[r1 * GSTR + col + 1] = gacc[nf][3];
            }
        }
        __syncthreads();

        for (int idx = tid; idx < 4096; idx += 256) {
            int t = idx >> 6, d = idx & 63;
            int grow = base + 64 + t;
            float bv = (grow < QLEN) ? rk[(size_t)grow * HD + n * 64 + d] : 0.f;
            __nv_bfloat16 h = __float2bfloat16(bv);
            bd_h[t * ROWP + d] = h;
            bd_l[t * ROWP + d] = __float2bfloat16(bv - __bfloat162float(h));
        }
        float sacc[4][4];
#pragma unroll
        for (int nf = 0; nf < 4; nf++)
#pragma unroll
            for (int i = 0; i < 4; i++) sacc[nf][i] = 0.f;
#pragma unroll
        for (int ks = 0; ks < 4; ks++) {
            int kb = ks * 16 + tg * 2;
            unsigned ah[4], al[4];
            ah[0] = *(unsigned*)&qw_h[r0 * ROWP + kb];
            ah[1] = *(unsigned*)&qw_h[r1 * ROWP + kb];
            ah[2] = *(unsigned*)&qw_h[r0 * ROWP + kb + 8];
            ah[3] = *(unsigned*)&qw_h[r1 * ROWP + kb + 8];
            al[0] = *(unsigned*)&qw_l[r0 * ROWP + kb];
            al[1] = *(unsigned*)&qw_l[r1 * ROWP + kb];
            al[2] = *(unsigned*)&qw_l[r0 * ROWP + kb + 8];
            al[3] = *(unsigned*)&qw_l[r1 * ROWP + kb + 8];
#pragma unroll
            for (int nf = 0; nf < 4; nf++) {
                int nn = ncol + nf * 8 + g;
                unsigned bh[2], bl[2];
                bh[0] = *(unsigned*)&kk_h[nn * ROWP + kb];
                bh[1] = *(unsigned*)&kk_h[nn * ROWP + kb + 8];
                bl[0] = *(unsigned*)&kk_l[nn * ROWP + kb];
                bl[1] = *(unsigned*)&kk_l[nn * ROWP + kb + 8];
                mma16816(sacc[nf], ah, bh);
                mma16816(sacc[nf], ah, bl);
                mma16816(sacc[nf], al, bh);
            }
        }
        __syncthreads();

        {
            float gacc[4][4];
#pragma unroll
            for (int nf = 0; nf < 4; nf++)
#pragma unroll
                for (int i = 0; i < 4; i++) gacc[nf][i] = 0.f;
#pragma unroll
            for (int ks = 0; ks < 4; ks++) {
                int kb = ks * 16 + tg * 2;
                unsigned ah[4], al[4];
                ah[0] = *(unsigned*)&qr_h[r0 * ROWP + kb];
                ah[1] = *(unsigned*)&qr_h[r1 * ROWP + kb];
                ah[2] = *(unsigned*)&qr_h[r0 * ROWP + kb + 8];
                ah[3] = *(unsigned*)&qr_h[r1 * ROWP + kb + 8];
                al[0] = *(unsigned*)&qr_l[r0 * ROWP + kb];
                al[1] = *(unsigned*)&qr_l[r1 * ROWP + kb];
                al[2] = *(unsigned*)&qr_l[r0 * ROWP + kb + 8];
                al[3] = *(unsigned*)&qr_l[r1 * ROWP + kb + 8];
#pragma unroll
                for (int nf = 0; nf < 4; nf++) {
                    int nn = ncol + nf * 8 + g;
                    unsigned bh[2], bl[2];
                    bh[0] = *(unsigned*)&bd_h[nn * ROWP + kb];
                    bh[1] = *(unsigned*)&bd_h[nn * ROWP + kb + 8];
                    bl[0] = *(unsigned*)&bd_l[nn * ROWP + kb];
                    bl[1] = *(unsigned*)&bd_l[nn * ROWP + kb + 8];
                    mma16816(gacc[nf], ah, bh);
                    mma16816(gacc[nf], ah, bl);
                    mma16816(gacc[nf], al, bh);
                }
            }
#pragma unroll
            for (int nf = 0; nf < 4; nf++) {
                int col = 64 + ncol + nf * 8 + tg * 2;
                G[r0 * GSTR + col]     = gacc[nf][0];
                G[r0 * GSTR + col + 1] = gacc[nf][1];
                G[r1 * GSTR + col]     = gacc[nf][2];
                G[r1 * GSTR + col + 1] = gacc[nf][3];
            }
        }
        __syncthreads();

        float rmax0 = -3.0e38f, rmax1 = -3.0e38f;
#pragma unroll
        for (int nf = 0; nf < 4; nf++) {
            int col = ncol + nf * 8 + tg * 2;
            float s00 = (sacc[nf][0] + G[r0 * GSTR + 63 - r0 + col])     * scale;
            float s01 = (sacc[nf][1] + G[r0 * GSTR + 63 - r0 + col + 1]) * scale;
            float s10 = (sacc[nf][2] + G[r1 * GSTR + 63 - r1 + col])     * scale;
            float s11 = (sacc[nf][3] + G[r1 * GSTR + 63 - r1 + col + 1]) * scale;
            int ir0 = i0 + r0, ir1 = i0 + r1;
            int jc = j0 + col;
            s00 = (jc     <= ir0) ? s00 : -1.0e30f;
            s01 = (jc + 1 <= ir0) ? s01 : -1.0e30f;
            s10 = (jc     <= ir1) ? s10 : -1.0e30f;
            s11 = (jc + 1 <= ir1) ? s11 : -1.0e30f;
            sacc[nf][0] = s00; sacc[nf][1] = s01;
            sacc[nf][2] = s10; sacc[nf][3] = s11;
            rmax0 = fmaxf(rmax0, fmaxf(s00, s01));
            rmax1 = fmaxf(rmax1, fmaxf(s10, s11));
        }
        rmax0 = fmaxf(rmax0, __shfl_xor_sync(0xffffffffu, rmax0, 1));
        rmax0 = fmaxf(rmax0, __shfl_xor_sync(0xffffffffu, rmax0, 2));
        rmax1 = fmaxf(rmax1, __shfl_xor_sync(0xffffffffu, rmax1, 1));
        rmax1 = fmaxf(rmax1, __shfl_xor_sync(0xffffffffu, rmax1, 2));
        if (tg == 0) { pmax[wn * 64 + r0] = rmax0; pmax[wn * 64 + r1] = rmax1; }
        __syncthreads();

        float nm0 = fmaxf(m_s[r0], fmaxf(pmax[r0], pmax[64 + r0]));
        float nm1 = fmaxf(m_s[r1], fmaxf(pmax[r1], pmax[64 + r1]));
        float rs0 = 0.f, rs1 = 0.f;
#pragma unroll
        for (int nf = 0; nf < 4; nf++) {
            int col = ncol + nf * 8 + tg * 2;
            float p00 = __expf(sacc[nf][0] - nm0);
            float p01 = __expf(sacc[nf][1] - nm0);
            float p10 = __expf(sacc[nf][2] - nm1);
            float p11 = __expf(sacc[nf][3] - nm1);
            rs0 += p00 + p01; rs1 += p10 + p11;
            __nv_bfloat16 h00 = __float2bfloat16(p00);
            __nv_bfloat16 h01 = __float2bfloat16(p01);
            __nv_bfloat16 h10 = __float2bfloat16(p10);
            __nv_bfloat16 h11 = __float2bfloat16(p11);
            *(unsigned*)&pp_h[r0 * ROWP + col] = pack_bf2(h00, h01);
            *(unsigned*)&pp_h[r1 * ROWP + col] = pack_bf2(h10, h11);
            *(unsigned*)&pp_l[r0 * ROWP + col] = pack_bf2(
                __float2bfloat16(p00 - __bfloat162float(h00)),
                __float2bfloat16(p01 - __bfloat162float(h01)));
            *(unsigned*)&pp_l[r1 * ROWP + col] = pack_bf2(
                __float2bfloat16(p10 - __bfloat162float(h10)),
                __float2bfloat16(p11 - __bfloat162float(h11)));
        }
        rs0 += __shfl_xor_sync(0xffffffffu, rs0, 1);
        rs0 += __shfl_xor_sync(0xffffffffu, rs0, 2);
        rs1 += __shfl_xor_sync(0xffffffffu, rs1, 1);
        rs1 += __shfl_xor_sync(0xffffffffu, rs1, 2);
        if (tg == 0) { psum[wn * 64 + r0] = rs0; psum[wn * 64 + r1] = rs1; }
        __syncthreads();

        if (tid < 64) {
            float mo = m_s[tid];
            float nm = fmaxf(mo, fmaxf(pmax[tid], pmax[64 + tid]));
            float co = __expf(mo - nm);
            corr_s[tid] = co;
            l_s[tid] = l_s[tid] * co + psum[tid] + psum[64 + tid];
            m_s[tid] = nm;
        }
        __syncthreads();

        float c0 = corr_s[r0], c1 = corr_s[r1];
#pragma unroll
        for (int nf = 0; nf < 4; nf++) {
            acc[nf][0] *= c0; acc[nf][1] *= c0;
            acc[nf][2] *= c1; acc[nf][3] *= c1;
        }
#pragma unroll
        for (int ks = 0; ks < 4; ks++) {
            int kb = ks * 16 + tg * 2;
            unsigned ah[4], al[4];
            ah[0] = *(unsigned*)&pp_h[r0 * ROWP + kb];
            ah[1] = *(unsigned*)&pp_h[r1 * ROWP + kb];
            ah[2] = *(unsigned*)&pp_h[r0 * ROWP + kb + 8];
            ah[3] = *(unsigned*)&pp_h[r1 * ROWP + kb + 8];
            al[0] = *(unsigned*)&pp_l[r0 * ROWP + kb];
            al[1] = *(unsigned*)&pp_l[r1 * ROWP + kb];
            al[2] = *(unsigned*)&pp_l[r0 * ROWP + kb + 8];
            al[3] = *(unsigned*)&pp_l[r1 * ROWP + kb + 8];
#pragma unroll
            for (int nf = 0; nf < 4; nf++) {
                int nn = ncol + nf * 8 + g;
                unsigned bh[2], bl[2];
                bh[0] = *(unsigned*)&vt_h[nn * ROWP + kb];
                bh[1] = *(unsigned*)&vt_h[nn * ROWP + kb + 8];
                bl[0] = *(unsigned*)&vt_l[nn * ROWP + kb];
                bl[1] = *(unsigned*)&vt_l[nn * ROWP + kb + 8];
                mma16816(acc[nf], ah, bh);
                mma16816(acc[nf], ah, bl);
                mma16816(acc[nf], al, bh);
            }
        }
    }

    float inv0 = 1.0f / l_s[r0];
    float inv1 = 1.0f / l_s[r1];
#pragma unroll
    for (int nf = 0; nf < 4; nf++) {
        int col = ncol + nf * 8 + tg * 2;
        size_t o0 = (size_t)((i0 + r0) * BSZ + b) * HD + n * 64 + col;
        size_t o1 = (size_t)((i0 + r1) * BSZ + b) * HD + n * 64 + col;
        *(float2*)&vec[o0] = make_float2(acc[nf][0] * inv0, acc[nf][1] * inv0);
        *(float2*)&vec[o1] = make_float2(acc[nf][2] * inv1, acc[nf][3] * inv1);
    }
}

// ---------------- residual + LayerNorm -------------------------------------
__global__ __launch_bounds__(256) void ln_kernel(
    const float* __restrict__ w, const float* __restrict__ ao,
    const float* __restrict__ gamma, const float* __restrict__ beta,
    float* __restrict__ out)
{
    int row = blockIdx.x;
    const float* wr = w  + (size_t)row * DM;
    const float* ar = ao + (size_t)row * DM;
    int tid = threadIdx.x;

    float x[4];
    float sum = 0.f, ssq = 0.f;
#pragma unroll
    for (int k = 0; k < 4; k++) {
        int d = tid + k * 256;
        x[k] = wr[d] + ar[d];
        sum += x[k];
        ssq += x[k] * x[k];
    }
#pragma unroll
    for (int o = 16; o > 0; o >>= 1) {
        sum += __shfl_xor_sync(0xffffffffu, sum, o);
        ssq += __shfl_xor_sync(0xffffffffu, ssq, o);
    }
    __shared__ float reds[8], redq[8];
    __shared__ float mu_s, rstd_s;
    int wid = tid >> 5, lane = tid & 31;
    if (lane == 0) { reds[wid] = sum; redq[wid] = ssq; }
    __syncthreads();
    if (tid == 0) {
        float s = 0.f, q = 0.f;
#pragma unroll
        for (int i = 0; i < 8; i++) { s += reds[i]; q += redq[i]; }
        float mu = s * (1.0f / DM);
        float var = q * (1.0f / DM) - mu * mu;
        mu_s = mu;
        rstd_s = rsqrtf(var + 1e-5f);
    }
    __syncthreads();
    float mu = mu_s, rstd = rstd_s;
#pragma unroll
    for (int k = 0; k < 4; k++) {
        int d = tid + k * 256;
        out[(size_t)row * DM + d] = (x[k] - mu) * rstd * gamma[d] + beta[d];
    }
}

// ---------------- launch ----------------------------------------------------
extern "C" void kernel_launch(void* const* d_in, const int* in_sizes, int n_in,
                              void* d_out, int out_size)
{
    const float* w    = (const float*)d_in[0];
    const float* r    = (const float*)d_in[1];
    const float* rwb  = (const float*)d_in[2];
    const float* rrb  = (const float*)d_in[3];
    // d_in[4] = attn_mask: deterministic causal tril -> applied analytically
    const float* Wqkv = (const float*)d_in[5];
    const float* Wr   = (const float*)d_in[6];
    const float* Wo   = (const float*)d_in[7];
    const float* gam  = (const float*)d_in[8];
    const float* bet  = (const float*)d_in[9];
    float* out = (float*)d_out;

    float *heads, *rkp, *vecp, *aop;
    cudaGetSymbolAddress((void**)&heads, g_heads);
    cudaGetSymbolAddress((void**)&rkp,   g_rk);
    cudaGetSymbolAddress((void**)&vecp,  g_vec);
    cudaGetSymbolAddress((void**)&aop,   g_ao);

    __nv_bfloat16 *wh, *wl, *vech, *vecl, *rh, *rl, *qkvTh, *qkvTl, *wrTh, *wrTl, *woTh, *woTl;
    cudaGetSymbolAddress((void**)&wh,    g_w_h);    cudaGetSymbolAddress((void**)&wl,    g_w_l);
    cudaGetSymbolAddress((void**)&vech,  g_vec_h);  cudaGetSymbolAddress((void**)&vecl,  g_vec_l);
    cudaGetSymbolAddress((void**)&rh,    g_r_h);    cudaGetSymbolAddress((void**)&rl,    g_r_l);
    cudaGetSymbolAddress((void**)&qkvTh, g_qkvT_h); cudaGetSymbolAddress((void**)&qkvTl, g_qkvT_l);
    cudaGetSymbolAddress((void**)&wrTh,  g_wrT_h);  cudaGetSymbolAddress((void**)&wrTl,  g_wrT_l);
    cudaGetSymbolAddress((void**)&woTh,  g_woT_h);  cudaGetSymbolAddress((void**)&woTl,  g_woT_l);

    // ---- one-time converts (recomputed every call; deterministic)
    conv_split<<<ROWS * DM / 1024, 256>>>(w, wh, wl, ROWS * DM);
    conv_split<<<QLEN * DM / 1024, 256>>>(r, rh, rl, QLEN * DM);
    conv_split_T<<<dim3(3*HD / 32, DM / 32), 256>>>(Wqkv, qkvTh, qkvTl, DM, 3*HD);
    conv_split_T<<<dim3(HD / 32, DM / 32), 256>>>(Wr, wrTh, wrTl, DM, HD);
    conv_split_T<<<dim3(DM / 32, HD / 32), 256>>>(Wo, woTh, woTl, HD, DM);

    cudaFuncSetAttribute(gemm_bf16, cudaFuncAttributeMaxDynamicSharedMemorySize,
                         GEMM_SMEM);

    // 1) heads = w @ W_qkv
    gemm_bf16<<<dim3(3072 / 128, 4096 / 128), 256, GEMM_SMEM>>>(
        wh, wl, qkvTh, qkvTl, heads, ROWS, 3 * HD, DM);
    // 2) r_k = r @ W_r
    gemm_bf16<<<dim3(HD / 128, QLEN / 128), 256, GEMM_SMEM>>>(
        rh, rl, wrTh, wrTl, rkp, QLEN, HD, DM);

    // 3) fused relative attention
    cudaFuncSetAttribute(attn_mma, cudaFuncAttributeMaxDynamicSharedMemorySize,
                         ATTN_SMEM);
    attn_mma<<<dim3(QLEN / 64, NH, BSZ), 256, ATTN_SMEM>>>(heads, rkp, rwb, rrb, vecp);

    // 4) attn_out = vec @ W_o
    conv_split<<<ROWS * HD / 1024, 256>>>(vecp, vech, vecl, ROWS * HD);
    gemm_bf16<<<dim3(DM / 128, ROWS / 128), 256, GEMM_SMEM>>>(
        vech, vecl, woTh, woTl, aop, ROWS, DM, HD);

    // 5) residual + layernorm
    ln_kernel<<<ROWS, 256>>>(w, aop, gam, bet, out);
}

// round 11
// speedup vs baseline: 1.4971x; 1.4971x over previous
#include <cuda_runtime.h>
#include <cuda_bf16.h>
#include <math.h>

#define QLEN 1024
#define BSZ 4
#define DM 1024
#define NH 16
#define DH 64
#define HD (NH*DH)          /* 1024 */
#define ROWS (QLEN*BSZ)     /* 4096 */

// ---------------- scratch (device globals; no allocation allowed) ----------
__device__ __align__(16) float g_heads[ROWS * 3 * HD];
__device__ __align__(16) float g_rk[QLEN * HD];
__device__ __align__(16) float g_vec[ROWS * HD];
__device__ __align__(16) float g_ao[ROWS * DM];

// ============================================================================
// helpers
// ============================================================================
__device__ __forceinline__ void mma16816(float* c, const unsigned* a, const unsigned* b)
{
    asm volatile(
        "mma.sync.aligned.m16n8k16.row.col.f32.bf16.bf16.f32 "
        "{%0,%1,%2,%3}, {%4,%5,%6,%7}, {%8,%9}, {%0,%1,%2,%3};\n"
        : "+f"(c[0]), "+f"(c[1]), "+f"(c[2]), "+f"(c[3])
        : "r"(a[0]), "r"(a[1]), "r"(a[2]), "r"(a[3]), "r"(b[0]), "r"(b[1]));
}

__device__ __forceinline__ unsigned pack_bf2(__nv_bfloat16 a, __nv_bfloat16 b)
{
    return ((unsigned)__bfloat16_as_ushort(b) << 16) | __bfloat16_as_ushort(a);
}

__device__ __forceinline__ void ldsm4(unsigned* r, const __nv_bfloat16* p)
{
    unsigned a = (unsigned)__cvta_generic_to_shared(p);
    asm volatile("ldmatrix.sync.aligned.m8n8.x4.shared.b16 {%0,%1,%2,%3}, [%4];\n"
                 : "=r"(r[0]), "=r"(r[1]), "=r"(r[2]), "=r"(r[3]) : "r"(a));
}

// 3-term bf16-split MMA block for attention tiles (stride 72):
// acc[4][4] += A[arow..arow+15][0..63] @ B[brow..brow+31][0..63]^T
__device__ __forceinline__ void mma_blk72(
    float (&acc)[4][4],
    const __nv_bfloat16* Ah, const __nv_bfloat16* Al, int arow,
    const __nv_bfloat16* Bh, const __nv_bfloat16* Bl, int brow, int lane)
{
    const int a_r = arow + (lane & 7) + ((lane >> 3) & 1) * 8;
    const int a_c = ((lane >> 4) & 1) * 8;
    const int b_r = brow + (lane & 7) + ((lane >> 4) & 1) * 8;
    const int b_c = ((lane >> 3) & 1) * 8;
#pragma unroll
    for (int ks = 0; ks < 4; ks++) {
        int kb = ks * 16;
        unsigned ah[4], al[4], bh[2][4], bl[2][4];
        ldsm4(ah, &Ah[a_r * 72 + kb + a_c]);
        ldsm4(al, &Al[a_r * 72 + kb + a_c]);
        ldsm4(bh[0], &Bh[b_r * 72 + kb + b_c]);
        ldsm4(bh[1], &Bh[(b_r + 16) * 72 + kb + b_c]);
        ldsm4(bl[0], &Bl[b_r * 72 + kb + b_c]);
        ldsm4(bl[1], &Bl[(b_r + 16) * 72 + kb + b_c]);
#pragma unroll
        for (int p = 0; p < 2; p++) {
            mma16816(acc[2*p],     ah, &bh[p][0]);
            mma16816(acc[2*p],     ah, &bl[p][0]);
            mma16816(acc[2*p],     al, &bh[p][0]);
            mma16816(acc[2*p + 1], ah, &bh[p][2]);
            mma16816(acc[2*p + 1], ah, &bl[p][2]);
            mma16816(acc[2*p + 1], al, &bh[p][2]);
        }
    }
}

// ============================================================================
// Tensor-core GEMM: C[M,N] = A[M,K] @ B[K,N], fp32 in/out, bf16 hi/lo split.
// 128x128x32 tile, 256 threads. Register prefetch + double-buffered smem +
// ldmatrix fragment loads. Requires M%128==0, N%128==0, K%32==0.
// ============================================================================
#define APAD 40
#define GTILE (128*APAD)
#define GEMM_SMEM (2 * 4 * GTILE * 2)   /* 81920 bytes */

__global__ __launch_bounds__(256) void gemm_mma(
    const float* __restrict__ A, const float* __restrict__ B,
    float* __restrict__ C, int M, int N, int K)
{
    extern __shared__ char smraw[];
    __nv_bfloat16* sm = (__nv_bfloat16*)smraw;

    const int tid  = threadIdx.x;
    const int row0 = blockIdx.y * 128;
    const int col0 = blockIdx.x * 128;
    const int warp = tid >> 5, lane = tid & 31;
    const int wm = warp & 1;
    const int wn = warp >> 1;
    const int g  = lane >> 2;
    const int tg = lane & 3;

    const int a_roff = (lane & 7) + ((lane >> 3) & 1) * 8;
    const int a_coff = ((lane >> 4) & 1) * 8;
    const int b_roff = (lane & 7) + ((lane >> 4) & 1) * 8;
    const int b_coff = ((lane >> 3) & 1) * 8;

    float acc[4][4][4];
#pragma unroll
    for (int mf = 0; mf < 4; mf++)
#pragma unroll
        for (int nf = 0; nf < 4; nf++)
#pragma unroll
            for (int i = 0; i < 4; i++) acc[mf][nf][i] = 0.f;

    float4 aV[4];
    float  bVf[16];

    auto ldg = [&](int k0) {
#pragma unroll
        for (int i = 0; i < 4; i++)
            aV[i] = *(const float4*)&A[(size_t)(row0 + (tid >> 3) + 32 * i) * K
                                       + k0 + (tid & 7) * 4];
#pragma unroll
        for (int i = 0; i < 16; i++) {
            int e = tid + i * 256;
            bVf[i] = B[(size_t)(k0 + (e >> 7)) * N + col0 + (e & 127)];
        }
    };

    auto sts = [&](int bsel) {
        __nv_bfloat16* sAh = sm + bsel * 4 * GTILE;
        __nv_bfloat16* sAl = sAh + GTILE;
        __nv_bfloat16* sBh = sAl + GTILE;
        __nv_bfloat16* sBl = sBh + GTILE;
#pragma unroll
        for (int i = 0; i < 4; i++) {
            int r = (tid >> 3) + 32 * i, kq = (tid & 7) * 4;
            float4 v = aV[i];
            __nv_bfloat16 h0 = __float2bfloat16(v.x);
            __nv_bfloat16 h1 = __float2bfloat16(v.y);
            __nv_bfloat16 h2 = __float2bfloat16(v.z);
            __nv_bfloat16 h3 = __float2bfloat16(v.w);
            *(unsigned*)&sAh[r * APAD + kq]     = pack_bf2(h0, h1);
            *(unsigned*)&sAh[r * APAD + kq + 2] = pack_bf2(h2, h3);
            *(unsigned*)&sAl[r * APAD + kq] = pack_bf2(
                __float2bfloat16(v.x - __bfloat162float(h0)),
                __float2bfloat16(v.y - __bfloat162float(h1)));
            *(unsigned*)&sAl[r * APAD + kq + 2] = pack_bf2(
                __float2bfloat16(v.z - __bfloat162float(h2)),
                __float2bfloat16(v.w - __bfloat162float(h3)));
        }
#pragma unroll
        for (int i = 0; i < 16; i++) {
            int e = tid + i * 256;
            int kk = e >> 7, nn = e & 127;
            float v = bVf[i];
            __nv_bfloat16 h = __float2bfloat16(v);
            sBh[nn * APAD + kk] = h;
            sBl[nn * APAD + kk] = __float2bfloat16(v - __bfloat162float(h));
        }
    };

    const int nk = K / 32;
    ldg(0);

    for (int it = 0; it < nk; it++) {
        sts(it & 1);
        __syncthreads();
        if (it + 1 < nk) ldg((it + 1) * 32);

        const __nv_bfloat16* cAh = sm + (it & 1) * 4 * GTILE;
        const __nv_bfloat16* cAl = cAh + GTILE;
        const __nv_bfloat16* cBh = cAl + GTILE;
        const __nv_bfloat16* cBl = cBh + GTILE;

#pragma unroll
        for (int ks = 0; ks < 2; ks++) {
            int kb = ks * 16;
            unsigned bh[2][4], bl[2][4];
            ldsm4(bh[0], &cBh[(wn * 32 + b_roff) * APAD + kb + b_coff]);
            ldsm4(bh[1], &cBh[(wn * 32 + 16 + b_roff) * APAD + kb + b_coff]);
            ldsm4(bl[0], &cBl[(wn * 32 + b_roff) * APAD + kb + b_coff]);
            ldsm4(bl[1], &cBl[(wn * 32 + 16 + b_roff) * APAD + kb + b_coff]);
#pragma unroll
            for (int mf = 0; mf < 4; mf++) {
                const int ar = wm * 64 + mf * 16 + a_roff;
                unsigned ah[4], al[4];
                ldsm4(ah, &cAh[ar * APAD + kb + a_coff]);
                ldsm4(al, &cAl[ar * APAD + kb + a_coff]);
#pragma unroll
                for (int p = 0; p < 2; p++) {
                    mma16816(acc[mf][2*p],     ah, &bh[p][0]);
                    mma16816(acc[mf][2*p],     ah, &bl[p][0]);
                    mma16816(acc[mf][2*p],     al, &bh[p][0]);
                    mma16816(acc[mf][2*p + 1], ah, &bh[p][2]);
                    mma16816(acc[mf][2*p + 1], ah, &bl[p][2]);
                    mma16816(acc[mf][2*p + 1], al, &bh[p][2]);
                }
            }
        }
    }

#pragma unroll
    for (int mf = 0; mf < 4; mf++) {
        int r = row0 + wm * 64 + mf * 16 + g;
#pragma unroll
        for (int nf = 0; nf < 4; nf++) {
            int c = col0 + wn * 32 + nf * 8 + tg * 2;
            *(float2*)&C[(size_t)r * N + c]       = make_float2(acc[mf][nf][0], acc[mf][nf][1]);
            *(float2*)&C[(size_t)(r + 8) * N + c] = make_float2(acc[mf][nf][2], acc[mf][nf][3]);
        }
    }
}

// ============================================================================
// Tensor-core fused rel-attention (flash-style, bf16-split MMAs, ldmatrix,
// band-buffer rotation). Grid (QLEN/64, NH, BSZ), 256 threads (8 warps).
// ============================================================================
#define ROWP 72
#define TBYTES (64*ROWP*2)        /* 9216 bytes per bf16 tile */
#define OFF_UNION (12*TBYTES)     /* G (f32 64x133) aliases P hi/lo */
#define GSTR 133
#define OFF_MISC (OFF_UNION + 64*GSTR*4)
#define ATTN_SMEM (OFF_MISC + 3*256 + 2*512)

__global__ __launch_bounds__(256) void attn_mma(
    const float* __restrict__ heads, const float* __restrict__ rk,
    const float* __restrict__ rwb, const float* __restrict__ rrb,
    float* __restrict__ vec)
{
    extern __shared__ char smc[];
    __nv_bfloat16* qw_h = (__nv_bfloat16*)(smc);
    __nv_bfloat16* qw_l = (__nv_bfloat16*)(smc + 1*TBYTES);
    __nv_bfloat16* qr_h = (__nv_bfloat16*)(smc + 2*TBYTES);
    __nv_bfloat16* qr_l = (__nv_bfloat16*)(smc + 3*TBYTES);
    __nv_bfloat16* kk_h = (__nv_bfloat16*)(smc + 4*TBYTES);
    __nv_bfloat16* kk_l = (__nv_bfloat16*)(smc + 5*TBYTES);
    __nv_bfloat16* vt_h = (__nv_bfloat16*)(smc + 6*TBYTES);
    __nv_bfloat16* vt_l = (__nv_bfloat16*)(smc + 7*TBYTES);
    __nv_bfloat16* bA_h = (__nv_bfloat16*)(smc + 8*TBYTES);   // band half0
    __nv_bfloat16* bA_l = (__nv_bfloat16*)(smc + 9*TBYTES);
    __nv_bfloat16* bB_h = (__nv_bfloat16*)(smc + 10*TBYTES);  // band half1
    __nv_bfloat16* bB_l = (__nv_bfloat16*)(smc + 11*TBYTES);
    __nv_bfloat16* pp_h = (__nv_bfloat16*)(smc + OFF_UNION);
    __nv_bfloat16* pp_l = (__nv_bfloat16*)(smc + OFF_UNION + TBYTES);
    float* G      = (float*)(smc + OFF_UNION);   // aliases pp (disjoint in time)
    float* m_s    = (float*)(smc + OFF_MISC);
    float* l_s    = (float*)(smc + OFF_MISC + 256);
    float* corr_s = (float*)(smc + OFF_MISC + 512);
    float* pmax   = (float*)(smc + OFF_MISC + 768);
    float* psum   = (float*)(smc + OFF_MISC + 1280);

    const int tid = threadIdx.x;
    const int warp = tid >> 5, lane = tid & 31;
    const int g = lane >> 2, tg = lane & 3;
    const int mrow = (warp & 3) * 16;
    const int ncol = (warp >> 2) * 32;
    const int wn = warp >> 2;
    const int i0 = blockIdx.x * 64;
    const int n  = blockIdx.y;
    const int b  = blockIdx.z;
    const int r0 = mrow + g, r1 = r0 + 8;

    // ---- Q load + biases, hi/lo split
    for (int idx = tid; idx < 4096; idx += 256) {
        int r = idx >> 6, d = idx & 63;
        float v = heads[(size_t)((i0 + r) * BSZ + b) * 3072 + n * 64 + d];
        float vw = v + rwb[n * 64 + d];
        float vr = v + rrb[n * 64 + d];
        __nv_bfloat16 h = __float2bfloat16(vw);
        qw_h[r * ROWP + d] = h;
        qw_l[r * ROWP + d] = __float2bfloat16(vw - __bfloat162float(h));
        h = __float2bfloat16(vr);
        qr_h[r * ROWP + d] = h;
        qr_l[r * ROWP + d] = __float2bfloat16(vr - __bfloat162float(h));
    }
    if (tid < 64) { m_s[tid] = -3.0e38f; l_s[tid] = 0.f; }

    float acc[4][4];
#pragma unroll
    for (int nf = 0; nf < 4; nf++)
#pragma unroll
        for (int i = 0; i < 4; i++) acc[nf][i] = 0.f;

    const float scale = 0.125f;
    const int ntiles = blockIdx.x + 1;

    for (int jt = 0; jt < ntiles; ++jt) {
        const int j0 = jt * 64;
        const int base = 960 - i0 + j0;
        __syncthreads();   // previous iter's smem reads complete

        // ---- K tile + V^T tile
        for (int idx = tid; idx < 4096; idx += 256) {
            int c = idx >> 6, d = idx & 63;
            size_t off = (size_t)((j0 + c) * BSZ + b) * 3072 + n * 64 + d;
            float kv = heads[off + 1024];
            float vv = heads[off + 2048];
            __nv_bfloat16 h = __float2bfloat16(kv);
            kk_h[c * ROWP + d] = h;
            kk_l[c * ROWP + d] = __float2bfloat16(kv - __bfloat162float(h));
            h = __float2bfloat16(vv);
            vt_h[d * ROWP + c] = h;
            vt_l[d * ROWP + c] = __float2bfloat16(vv - __bfloat162float(h));
        }
        // ---- band half1 -> bB (masked only on the final iteration, which is
        // never reused as half0 -> rotation is safe)
        for (int idx = tid; idx < 4096; idx += 256) {
            int t = idx >> 6, d = idx & 63;
            int grow = base + 64 + t;
            float bv = (grow < QLEN) ? rk[(size_t)grow * HD + n * 64 + d] : 0.f;
            __nv_bfloat16 h = __float2bfloat16(bv);
            bB_h[t * ROWP + d] = h;
            bB_l[t * ROWP + d] = __float2bfloat16(bv - __bfloat162float(h));
        }
        if (jt == 0) {
            // first iteration: also load half0 into bA (rows base..base+63 < QLEN)
            for (int idx = tid; idx < 4096; idx += 256) {
                int t = idx >> 6, d = idx & 63;
                float bv = rk[(size_t)(base + t) * HD + n * 64 + d];
                __nv_bfloat16 h = __float2bfloat16(bv);
                bA_h[t * ROWP + d] = h;
                bA_l[t * ROWP + d] = __float2bfloat16(bv - __bfloat162float(h));
            }
        }
        __syncthreads();

        // ---- G half0 = Qr @ bandA^T
        {
            float gacc[4][4];
#pragma unroll
            for (int nf = 0; nf < 4; nf++)
#pragma unroll
                for (int i = 0; i < 4; i++) gacc[nf][i] = 0.f;
            mma_blk72(gacc, qr_h, qr_l, mrow, bA_h, bA_l, ncol, lane);
#pragma unroll
            for (int nf = 0; nf < 4; nf++) {
                int col = ncol + nf * 8 + tg * 2;
                G[r0 * GSTR + col]     = gacc[nf][0];
                G[r0 * GSTR + col + 1] = gacc[nf][1];
                G[r1 * GSTR + col]     = gacc[nf][2];
                G[r1 * GSTR + col + 1] = gacc[nf][3];
            }
        }

        // ---- AC = Qw @ K^T
        float sacc[4][4];
#pragma unroll
        for (int nf = 0; nf < 4; nf++)
#pragma unroll
            for (int i = 0; i < 4; i++) sacc[nf][i] = 0.f;
        mma_blk72(sacc, qw_h, qw_l, mrow, kk_h, kk_l, ncol, lane);

        // ---- G half1 = Qr @ bandB^T
        {
            float gacc[4][4];
#pragma unroll
            for (int nf = 0; nf < 4; nf++)
#pragma unroll
                for (int i = 0; i < 4; i++) gacc[nf][i] = 0.f;
            mma_blk72(gacc, qr_h, qr_l, mrow, bB_h, bB_l, ncol, lane);
#pragma unroll
            for (int nf = 0; nf < 4; nf++) {
                int col = 64 + ncol + nf * 8 + tg * 2;
                G[r0 * GSTR + col]     = gacc[nf][0];
                G[r0 * GSTR + col + 1] = gacc[nf][1];
                G[r1 * GSTR + col]     = gacc[nf][2];
                G[r1 * GSTR + col + 1] = gacc[nf][3];
            }
        }
        __syncthreads();   // G complete

        // ---- s = (AC + G[r][63-r+c])*scale, causal mask, row max
        float rmax0 = -3.0e38f, rmax1 = -3.0e38f;
#pragma unroll
        for (int nf = 0; nf < 4; nf++) {
            int col = ncol + nf * 8 + tg * 2;
            float s00 = (sacc[nf][0] + G[r0 * GSTR + 63 - r0 + col])     * scale;
            float s01 = (sacc[nf][1] + G[r0 * GSTR + 63 - r0 + col + 1]) * scale;
            float s10 = (sacc[nf][2] + G[r1 * GSTR + 63 - r1 + col])     * scale;
            float s11 = (sacc[nf][3] + G[r1 * GSTR + 63 - r1 + col + 1]) * scale;
            int ir0 = i0 + r0, ir1 = i0 + r1;
            int jc = j0 + col;
            s00 = (jc     <= ir0) ? s00 : -1.0e30f;
            s01 = (jc + 1 <= ir0) ? s01 : -1.0e30f;
            s10 = (jc     <= ir1) ? s10 : -1.0e30f;
            s11 = (jc + 1 <= ir1) ? s11 : -1.0e30f;
            sacc[nf][0] = s00; sacc[nf][1] = s01;
            sacc[nf][2] = s10; sacc[nf][3] = s11;
            rmax0 = fmaxf(rmax0, fmaxf(s00, s01));
            rmax1 = fmaxf(rmax1, fmaxf(s10, s11));
        }
        rmax0 = fmaxf(rmax0, __shfl_xor_sync(0xffffffffu, rmax0, 1));
        rmax0 = fmaxf(rmax0, __shfl_xor_sync(0xffffffffu, rmax0, 2));
        rmax1 = fmaxf(rmax1, __shfl_xor_sync(0xffffffffu, rmax1, 1));
        rmax1 = fmaxf(rmax1, __shfl_xor_sync(0xffffffffu, rmax1, 2));
        if (tg == 0) { pmax[wn * 64 + r0] = rmax0; pmax[wn * 64 + r1] = rmax1; }
        __syncthreads();

        // ---- exp + P write (aliases G; all G reads done above)
        float nm0 = fmaxf(m_s[r0], fmaxf(pmax[r0], pmax[64 + r0]));
        float nm1 = fmaxf(m_s[r1], fmaxf(pmax[r1], pmax[64 + r1]));
        float rs0 = 0.f, rs1 = 0.f;
#pragma unroll
        for (int nf = 0; nf < 4; nf++) {
            int col = ncol + nf * 8 + tg * 2;
            float p00 = __expf(sacc[nf][0] - nm0);
            float p01 = __expf(sacc[nf][1] - nm0);
            float p10 = __expf(sacc[nf][2] - nm1);
            float p11 = __expf(sacc[nf][3] - nm1);
            rs0 += p00 + p01; rs1 += p10 + p11;
            __nv_bfloat16 h00 = __float2bfloat16(p00);
            __nv_bfloat16 h01 = __float2bfloat16(p01);
            __nv_bfloat16 h10 = __float2bfloat16(p10);
            __nv_bfloat16 h11 = __float2bfloat16(p11);
            *(unsigned*)&pp_h[r0 * ROWP + col] = pack_bf2(h00, h01);
            *(unsigned*)&pp_h[r1 * ROWP + col] = pack_bf2(h10, h11);
            *(unsigned*)&pp_l[r0 * ROWP + col] = pack_bf2(
                __float2bfloat16(p00 - __bfloat162float(h00)),
                __float2bfloat16(p01 - __bfloat162float(h01)));
            *(unsigned*)&pp_l[r1 * ROWP + col] = pack_bf2(
                __float2bfloat16(p10 - __bfloat162float(h10)),
                __float2bfloat16(p11 - __bfloat162float(h11)));
        }
        rs0 += __shfl_xor_sync(0xffffffffu, rs0, 1);
        rs0 += __shfl_xor_sync(0xffffffffu, rs0, 2);
        rs1 += __shfl_xor_sync(0xffffffffu, rs1, 1);
        rs1 += __shfl_xor_sync(0xffffffffu, rs1, 2);
        if (tg == 0) { psum[wn * 64 + r0] = rs0; psum[wn * 64 + r1] = rs1; }
        __syncthreads();

        // ---- flash state update
        if (tid < 64) {
            float mo = m_s[tid];
            float nm = fmaxf(mo, fmaxf(pmax[tid], pmax[64 + tid]));
            float co = __expf(mo - nm);
            corr_s[tid] = co;
            l_s[tid] = l_s[tid] * co + psum[tid] + psum[64 + tid];
            m_s[tid] = nm;
        }
        __syncthreads();

        // ---- PV: acc = acc*corr + P @ V^T
        float c0 = corr_s[r0], c1 = corr_s[r1];
#pragma unroll
        for (int nf = 0; nf < 4; nf++) {
            acc[nf][0] *= c0; acc[nf][1] *= c0;
            acc[nf][2] *= c1; acc[nf][3] *= c1;
        }
        mma_blk72(acc, pp_h, pp_l, mrow, vt_h, vt_l, ncol, lane);

        // ---- rotate band buffers: this half1 becomes next half0
        __nv_bfloat16* t;
        t = bA_h; bA_h = bB_h; bB_h = t;
        t = bA_l; bA_l = bB_l; bB_l = t;
    }

    float inv0 = 1.0f / l_s[r0];
    float inv1 = 1.0f / l_s[r1];
#pragma unroll
    for (int nf = 0; nf < 4; nf++) {
        int col = ncol + nf * 8 + tg * 2;
        size_t o0 = (size_t)((i0 + r0) * BSZ + b) * HD + n * 64 + col;
        size_t o1 = (size_t)((i0 + r1) * BSZ + b) * HD + n * 64 + col;
        *(float2*)&vec[o0] = make_float2(acc[nf][0] * inv0, acc[nf][1] * inv0);
        *(float2*)&vec[o1] = make_float2(acc[nf][2] * inv1, acc[nf][3] * inv1);
    }
}

// ---------------- residual + LayerNorm -------------------------------------
__global__ __launch_bounds__(256) void ln_kernel(
    const float* __restrict__ w, const float* __restrict__ ao,
    const float* __restrict__ gamma, const float* __restrict__ beta,
    float* __restrict__ out)
{
    int row = blockIdx.x;
    const float* wr = w  + (size_t)row * DM;
    const float* ar = ao + (size_t)row * DM;
    int tid = threadIdx.x;

    float x[4];
    float sum = 0.f, ssq = 0.f;
#pragma unroll
    for (int k = 0; k < 4; k++) {
        int d = tid + k * 256;
        x[k] = wr[d] + ar[d];
        sum += x[k];
        ssq += x[k] * x[k];
    }
#pragma unroll
    for (int o = 16; o > 0; o >>= 1) {
        sum += __shfl_xor_sync(0xffffffffu, sum, o);
        ssq += __shfl_xor_sync(0xffffffffu, ssq, o);
    }
    __shared__ float reds[8], redq[8];
    __shared__ float mu_s, rstd_s;
    int wid = tid >> 5, lane = tid & 31;
    if (lane == 0) { reds[wid] = sum; redq[wid] = ssq; }
    __syncthreads();
    if (tid == 0) {
        float s = 0.f, q = 0.f;
#pragma unroll
        for (int i = 0; i < 8; i++) { s += reds[i]; q += redq[i]; }
        float mu = s * (1.0f / DM);
        float var = q * (1.0f / DM) - mu * mu;
        mu_s = mu;
        rstd_s = rsqrtf(var + 1e-5f);
    }
    __syncthreads();
    float mu = mu_s, rstd = rstd_s;
#pragma unroll
    for (int k = 0; k < 4; k++) {
        int d = tid + k * 256;
        out[(size_t)row * DM + d] = (x[k] - mu) * rstd * gamma[d] + beta[d];
    }
}

// ---------------- launch ----------------------------------------------------
extern "C" void kernel_launch(void* const* d_in, const int* in_sizes, int n_in,
                              void* d_out, int out_size)
{
    const float* w    = (const float*)d_in[0];
    const float* r    = (const float*)d_in[1];
    const float* rwb  = (const float*)d_in[2];
    const float* rrb  = (const float*)d_in[3];
    // d_in[4] = attn_mask: deterministic causal tril -> applied analytically
    const float* Wqkv = (const float*)d_in[5];
    const float* Wr   = (const float*)d_in[6];
    const float* Wo   = (const float*)d_in[7];
    const float* gam  = (const float*)d_in[8];
    const float* bet  = (const float*)d_in[9];
    float* out = (float*)d_out;

    float *heads, *rkp, *vecp, *aop;
    cudaGetSymbolAddress((void**)&heads, g_heads);
    cudaGetSymbolAddress((void**)&rkp,   g_rk);
    cudaGetSymbolAddress((void**)&vecp,  g_vec);
    cudaGetSymbolAddress((void**)&aop,   g_ao);

    cudaFuncSetAttribute(gemm_mma, cudaFuncAttributeMaxDynamicSharedMemorySize,
                         GEMM_SMEM);
    cudaFuncSetAttribute(attn_mma, cudaFuncAttributeMaxDynamicSharedMemorySize,
                         ATTN_SMEM);

    // 1) heads = w @ W_qkv
    gemm_mma<<<dim3(3072 / 128, 4096 / 128), 256, GEMM_SMEM>>>(
        w, Wqkv, heads, ROWS, 3 * HD, DM);
    // 2) r_k = r @ W_r
    gemm_mma<<<dim3(HD / 128, QLEN / 128), 256, GEMM_SMEM>>>(
        r, Wr, rkp, QLEN, HD, DM);

    // 3) fused relative attention
    attn_mma<<<dim3(QLEN / 64, NH, BSZ), 256, ATTN_SMEM>>>(heads, rkp, rwb, rrb, vecp);

    // 4) attn_out = vec @ W_o
    gemm_mma<<<dim3(DM / 128, ROWS / 128), 256, GEMM_SMEM>>>(
        vecp, Wo, aop, ROWS, DM, HD);

    // 5) residual + layernorm
    ln_kernel<<<ROWS, 256>>>(w, aop, gam, bet, out);
}

// round 12
// speedup vs baseline: 1.7759x; 1.1862x over previous
#include <cuda_runtime.h>
#include <cuda_bf16.h>
#include <math.h>

#define QLEN 1024
#define BSZ 4
#define DM 1024
#define NH 16
#define DH 64
#define HD (NH*DH)          /* 1024 */
#define ROWS (QLEN*BSZ)     /* 4096 */

// ---------------- scratch (device globals; no allocation allowed) ----------
__device__ __align__(16) float g_heads[ROWS * 3 * HD];
__device__ __align__(16) float g_rk[QLEN * HD];
__device__ __align__(16) float g_vec[ROWS * HD];
__device__ __align__(16) float g_ao[ROWS * DM];

// ============================================================================
// helpers
// ============================================================================
__device__ __forceinline__ void mma16816(float* c, const unsigned* a, const unsigned* b)
{
    asm volatile(
        "mma.sync.aligned.m16n8k16.row.col.f32.bf16.bf16.f32 "
        "{%0,%1,%2,%3}, {%4,%5,%6,%7}, {%8,%9}, {%0,%1,%2,%3};\n"
        : "+f"(c[0]), "+f"(c[1]), "+f"(c[2]), "+f"(c[3])
        : "r"(a[0]), "r"(a[1]), "r"(a[2]), "r"(a[3]), "r"(b[0]), "r"(b[1]));
}

__device__ __forceinline__ unsigned pack_bf2(__nv_bfloat16 a, __nv_bfloat16 b)
{
    return ((unsigned)__bfloat16_as_ushort(b) << 16) | __bfloat16_as_ushort(a);
}

// split a float4 into hi (uint2) and lo (uint2) packed bf16 pairs
__device__ __forceinline__ void split4(float4 v, uint2& hv, uint2& lv)
{
    __nv_bfloat16 h0 = __float2bfloat16(v.x);
    __nv_bfloat16 h1 = __float2bfloat16(v.y);
    __nv_bfloat16 h2 = __float2bfloat16(v.z);
    __nv_bfloat16 h3 = __float2bfloat16(v.w);
    hv.x = pack_bf2(h0, h1);
    hv.y = pack_bf2(h2, h3);
    lv.x = pack_bf2(__float2bfloat16(v.x - __bfloat162float(h0)),
                    __float2bfloat16(v.y - __bfloat162float(h1)));
    lv.y = pack_bf2(__float2bfloat16(v.z - __bfloat162float(h2)),
                    __float2bfloat16(v.w - __bfloat162float(h3)));
}

__device__ __forceinline__ void ldsm4(unsigned* r, const __nv_bfloat16* p)
{
    unsigned a = (unsigned)__cvta_generic_to_shared(p);
    asm volatile("ldmatrix.sync.aligned.m8n8.x4.shared.b16 {%0,%1,%2,%3}, [%4];\n"
                 : "=r"(r[0]), "=r"(r[1]), "=r"(r[2]), "=r"(r[3]) : "r"(a));
}

// 3-term bf16-split MMA block for attention tiles (stride 72):
// acc[4][4] += A[arow..arow+15][0..63] @ B[brow..brow+31][0..63]^T
__device__ __forceinline__ void mma_blk72(
    float (&acc)[4][4],
    const __nv_bfloat16* Ah, const __nv_bfloat16* Al, int arow,
    const __nv_bfloat16* Bh, const __nv_bfloat16* Bl, int brow, int lane)
{
    const int a_r = arow + (lane & 7) + ((lane >> 3) & 1) * 8;
    const int a_c = ((lane >> 4) & 1) * 8;
    const int b_r = brow + (lane & 7) + ((lane >> 4) & 1) * 8;
    const int b_c = ((lane >> 3) & 1) * 8;
#pragma unroll
    for (int ks = 0; ks < 4; ks++) {
        int kb = ks * 16;
        unsigned ah[4], al[4], bh[2][4], bl[2][4];
        ldsm4(ah, &Ah[a_r * 72 + kb + a_c]);
        ldsm4(al, &Al[a_r * 72 + kb + a_c]);
        ldsm4(bh[0], &Bh[b_r * 72 + kb + b_c]);
        ldsm4(bh[1], &Bh[(b_r + 16) * 72 + kb + b_c]);
        ldsm4(bl[0], &Bl[b_r * 72 + kb + b_c]);
        ldsm4(bl[1], &Bl[(b_r + 16) * 72 + kb + b_c]);
#pragma unroll
        for (int p = 0; p < 2; p++) {
            mma16816(acc[2*p],     ah, &bh[p][0]);
            mma16816(acc[2*p],     ah, &bl[p][0]);
            mma16816(acc[2*p],     al, &bh[p][0]);
            mma16816(acc[2*p + 1], ah, &bh[p][2]);
            mma16816(acc[2*p + 1], ah, &bl[p][2]);
            mma16816(acc[2*p + 1], al, &bh[p][2]);
        }
    }
}

// ============================================================================
// Tensor-core GEMM: C[M,N] = A[M,K] @ B[K,N], fp32 in/out, bf16 hi/lo split.
// 128x128x32 tile, 256 threads. Register prefetch + double-buffered smem +
// ldmatrix fragment loads + STS.64 vectorized fills.
// ============================================================================
#define APAD 40
#define GTILE (128*APAD)
#define GEMM_SMEM (2 * 4 * GTILE * 2)   /* 81920 bytes */

__global__ __launch_bounds__(256) void gemm_mma(
    const float* __restrict__ A, const float* __restrict__ B,
    float* __restrict__ C, int M, int N, int K)
{
    extern __shared__ char smraw[];
    __nv_bfloat16* sm = (__nv_bfloat16*)smraw;

    const int tid  = threadIdx.x;
    const int row0 = blockIdx.y * 128;
    const int col0 = blockIdx.x * 128;
    const int warp = tid >> 5, lane = tid & 31;
    const int wm = warp & 1;
    const int wn = warp >> 1;
    const int g  = lane >> 2;
    const int tg = lane & 3;

    const int a_roff = (lane & 7) + ((lane >> 3) & 1) * 8;
    const int a_coff = ((lane >> 4) & 1) * 8;
    const int b_roff = (lane & 7) + ((lane >> 4) & 1) * 8;
    const int b_coff = ((lane >> 3) & 1) * 8;

    float acc[4][4][4];
#pragma unroll
    for (int mf = 0; mf < 4; mf++)
#pragma unroll
        for (int nf = 0; nf < 4; nf++)
#pragma unroll
            for (int i = 0; i < 4; i++) acc[mf][nf][i] = 0.f;

    float4 aV[4];     // A: 4 rows x 4 k
    float4 bV[4];     // B: 4 (n, k-quad) groups

    auto ldg = [&](int k0) {
#pragma unroll
        for (int i = 0; i < 4; i++)
            aV[i] = *(const float4*)&A[(size_t)(row0 + (tid >> 3) + 32 * i) * K
                                       + k0 + (tid & 7) * 4];
#pragma unroll
        for (int i = 0; i < 4; i++) {
            int e = tid + i * 256;        // 0..1023
            int kq = e >> 7;              // 0..7 (k-quad)
            int nn = e & 127;
            // 4 strided-k loads, coalesced across n within each j
            bV[i].x = B[(size_t)(k0 + kq * 4 + 0) * N + col0 + nn];
            bV[i].y = B[(size_t)(k0 + kq * 4 + 1) * N + col0 + nn];
            bV[i].z = B[(size_t)(k0 + kq * 4 + 2) * N + col0 + nn];
            bV[i].w = B[(size_t)(k0 + kq * 4 + 3) * N + col0 + nn];
        }
    };

    auto sts = [&](int bsel) {
        __nv_bfloat16* sAh = sm + bsel * 4 * GTILE;
        __nv_bfloat16* sAl = sAh + GTILE;
        __nv_bfloat16* sBh = sAl + GTILE;
        __nv_bfloat16* sBl = sBh + GTILE;
#pragma unroll
        for (int i = 0; i < 4; i++) {
            int r = (tid >> 3) + 32 * i, kq = (tid & 7) * 4;
            uint2 hv, lv;
            split4(aV[i], hv, lv);
            *(uint2*)&sAh[r * APAD + kq] = hv;
            *(uint2*)&sAl[r * APAD + kq] = lv;
        }
#pragma unroll
        for (int i = 0; i < 4; i++) {
            int e = tid + i * 256;
            int kq = e >> 7;
            int nn = e & 127;
            uint2 hv, lv;
            split4(bV[i], hv, lv);
            *(uint2*)&sBh[nn * APAD + kq * 4] = hv;
            *(uint2*)&sBl[nn * APAD + kq * 4] = lv;
        }
    };

    const int nk = K / 32;
    ldg(0);

    for (int it = 0; it < nk; it++) {
        sts(it & 1);
        __syncthreads();
        if (it + 1 < nk) ldg((it + 1) * 32);

        const __nv_bfloat16* cAh = sm + (it & 1) * 4 * GTILE;
        const __nv_bfloat16* cAl = cAh + GTILE;
        const __nv_bfloat16* cBh = cAl + GTILE;
        const __nv_bfloat16* cBl = cBh + GTILE;

#pragma unroll
        for (int ks = 0; ks < 2; ks++) {
            int kb = ks * 16;
            unsigned bh[2][4], bl[2][4];
            ldsm4(bh[0], &cBh[(wn * 32 + b_roff) * APAD + kb + b_coff]);
            ldsm4(bh[1], &cBh[(wn * 32 + 16 + b_roff) * APAD + kb + b_coff]);
            ldsm4(bl[0], &cBl[(wn * 32 + b_roff) * APAD + kb + b_coff]);
            ldsm4(bl[1], &cBl[(wn * 32 + 16 + b_roff) * APAD + kb + b_coff]);
#pragma unroll
            for (int mf = 0; mf < 4; mf++) {
                const int ar = wm * 64 + mf * 16 + a_roff;
                unsigned ah[4], al[4];
                ldsm4(ah, &cAh[ar * APAD + kb + a_coff]);
                ldsm4(al, &cAl[ar * APAD + kb + a_coff]);
#pragma unroll
                for (int p = 0; p < 2; p++) {
                    mma16816(acc[mf][2*p],     ah, &bh[p][0]);
                    mma16816(acc[mf][2*p],     ah, &bl[p][0]);
                    mma16816(acc[mf][2*p],     al, &bh[p][0]);
                    mma16816(acc[mf][2*p + 1], ah, &bh[p][2]);
                    mma16816(acc[mf][2*p + 1], ah, &bl[p][2]);
                    mma16816(acc[mf][2*p + 1], al, &bh[p][2]);
                }
            }
        }
    }

#pragma unroll
    for (int mf = 0; mf < 4; mf++) {
        int r = row0 + wm * 64 + mf * 16 + g;
#pragma unroll
        for (int nf = 0; nf < 4; nf++) {
            int c = col0 + wn * 32 + nf * 8 + tg * 2;
            *(float2*)&C[(size_t)r * N + c]       = make_float2(acc[mf][nf][0], acc[mf][nf][1]);
            *(float2*)&C[(size_t)(r + 8) * N + c] = make_float2(acc[mf][nf][2], acc[mf][nf][3]);
        }
    }
}

// ============================================================================
// Tensor-core fused rel-attention (flash-style, bf16-split MMAs, ldmatrix,
// band rotation, float4 register-staged prefetch of K/V/band).
// Grid (QLEN/64, NH, BSZ), 256 threads (8 warps).
// ============================================================================
#define ROWP 72
#define TBYTES (64*ROWP*2)        /* 9216 bytes per bf16 tile */
#define OFF_UNION (12*TBYTES)     /* G (f32 64x133) aliases P hi/lo */
#define GSTR 133
#define OFF_MISC (OFF_UNION + 64*GSTR*4)
#define ATTN_SMEM (OFF_MISC + 3*256 + 2*512)

__global__ __launch_bounds__(256) void attn_mma(
    const float* __restrict__ heads, const float* __restrict__ rk,
    const float* __restrict__ rwb, const float* __restrict__ rrb,
    float* __restrict__ vec)
{
    extern __shared__ char smc[];
    __nv_bfloat16* qw_h = (__nv_bfloat16*)(smc);
    __nv_bfloat16* qw_l = (__nv_bfloat16*)(smc + 1*TBYTES);
    __nv_bfloat16* qr_h = (__nv_bfloat16*)(smc + 2*TBYTES);
    __nv_bfloat16* qr_l = (__nv_bfloat16*)(smc + 3*TBYTES);
    __nv_bfloat16* kk_h = (__nv_bfloat16*)(smc + 4*TBYTES);
    __nv_bfloat16* kk_l = (__nv_bfloat16*)(smc + 5*TBYTES);
    __nv_bfloat16* vt_h = (__nv_bfloat16*)(smc + 6*TBYTES);
    __nv_bfloat16* vt_l = (__nv_bfloat16*)(smc + 7*TBYTES);
    __nv_bfloat16* bA_h = (__nv_bfloat16*)(smc + 8*TBYTES);   // band half0
    __nv_bfloat16* bA_l = (__nv_bfloat16*)(smc + 9*TBYTES);
    __nv_bfloat16* bB_h = (__nv_bfloat16*)(smc + 10*TBYTES);  // band half1
    __nv_bfloat16* bB_l = (__nv_bfloat16*)(smc + 11*TBYTES);
    __nv_bfloat16* pp_h = (__nv_bfloat16*)(smc + OFF_UNION);
    __nv_bfloat16* pp_l = (__nv_bfloat16*)(smc + OFF_UNION + TBYTES);
    float* G      = (float*)(smc + OFF_UNION);   // aliases pp (disjoint in time)
    float* m_s    = (float*)(smc + OFF_MISC);
    float* l_s    = (float*)(smc + OFF_MISC + 256);
    float* corr_s = (float*)(smc + OFF_MISC + 512);
    float* pmax   = (float*)(smc + OFF_MISC + 768);
    float* psum   = (float*)(smc + OFF_MISC + 1280);

    const int tid = threadIdx.x;
    const int warp = tid >> 5, lane = tid & 31;
    const int g = lane >> 2, tg = lane & 3;
    const int mrow = (warp & 3) * 16;
    const int ncol = (warp >> 2) * 32;
    const int wn = warp >> 2;
    const int i0 = blockIdx.x * 64;
    const int n  = blockIdx.y;
    const int b  = blockIdx.z;
    const int r0 = mrow + g, r1 = r0 + 8;

    // ---- Q load + biases, hi/lo split
    for (int idx = tid; idx < 4096; idx += 256) {
        int r = idx >> 6, d = idx & 63;
        float v = heads[(size_t)((i0 + r) * BSZ + b) * 3072 + n * 64 + d];
        float vw = v + rwb[n * 64 + d];
        float vr = v + rrb[n * 64 + d];
        __nv_bfloat16 h = __float2bfloat16(vw);
        qw_h[r * ROWP + d] = h;
        qw_l[r * ROWP + d] = __float2bfloat16(vw - __bfloat162float(h));
        h = __float2bfloat16(vr);
        qr_h[r * ROWP + d] = h;
        qr_l[r * ROWP + d] = __float2bfloat16(vr - __bfloat162float(h));
    }
    if (tid < 64) { m_s[tid] = -3.0e38f; l_s[tid] = 0.f; }

    // ---- band half0 for jt=0 (rows base0..base0+63, all < QLEN) direct store
    {
        const int base0 = 960 - i0;
#pragma unroll
        for (int i = 0; i < 4; i++) {
            int ch = tid + i * 256;          // 0..1023
            int t = ch >> 4, dq = (ch & 15) * 4;
            float4 v = *(const float4*)&rk[(size_t)(base0 + t) * HD + n * 64 + dq];
            uint2 hv, lv;
            split4(v, hv, lv);
            *(uint2*)&bA_h[t * ROWP + dq] = hv;
            *(uint2*)&bA_l[t * ROWP + dq] = lv;
        }
    }

    float4 kV[4], vV[4], bV[4];   // register staging for next tile

    auto ldg_tile = [&](int j0, int base) {
#pragma unroll
        for (int i = 0; i < 4; i++) {
            int ch = tid + i * 256;
            int c = ch >> 4, dq = (ch & 15) * 4;
            size_t off = (size_t)((j0 + c) * BSZ + b) * 3072 + n * 64 + dq;
            kV[i] = *(const float4*)&heads[off + 1024];
            vV[i] = *(const float4*)&heads[off + 2048];
            int grow = base + 64 + c;
            if (grow < QLEN)
                bV[i] = *(const float4*)&rk[(size_t)grow * HD + n * 64 + dq];
            else
                bV[i] = make_float4(0.f, 0.f, 0.f, 0.f);
        }
    };

    float acc[4][4];
#pragma unroll
    for (int nf = 0; nf < 4; nf++)
#pragma unroll
        for (int i = 0; i < 4; i++) acc[nf][i] = 0.f;

    const float scale = 0.125f;
    const int ntiles = blockIdx.x + 1;

    ldg_tile(0, 960 - i0);   // prologue: stage jt=0 K/V/band-half1

    for (int jt = 0; jt < ntiles; ++jt) {
        const int j0 = jt * 64;
        __syncthreads();   // previous iter's smem reads complete

        // ---- STS staged K / V^T / band-half1 (fast: no LDG latency here)
#pragma unroll
        for (int i = 0; i < 4; i++) {
            int ch = tid + i * 256;
            int c = ch >> 4, dq = (ch & 15) * 4;
            uint2 hv, lv;
            split4(kV[i], hv, lv);
            *(uint2*)&kk_h[c * ROWP + dq] = hv;
            *(uint2*)&kk_l[c * ROWP + dq] = lv;
            split4(bV[i], hv, lv);
            *(uint2*)&bB_h[c * ROWP + dq] = hv;
            *(uint2*)&bB_l[c * ROWP + dq] = lv;
            // V transposed: scalar stores
            float4 vv = vV[i];
            __nv_bfloat16 h;
            h = __float2bfloat16(vv.x);
            vt_h[(dq + 0) * ROWP + c] = h;
            vt_l[(dq + 0) * ROWP + c] = __float2bfloat16(vv.x - __bfloat162float(h));
            h = __float2bfloat16(vv.y);
            vt_h[(dq + 1) * ROWP + c] = h;
            vt_l[(dq + 1) * ROWP + c] = __float2bfloat16(vv.y - __bfloat162float(h));
            h = __float2bfloat16(vv.z);
            vt_h[(dq + 2) * ROWP + c] = h;
            vt_l[(dq + 2) * ROWP + c] = __float2bfloat16(vv.z - __bfloat162float(h));
            h = __float2bfloat16(vv.w);
            vt_h[(dq + 3) * ROWP + c] = h;
            vt_l[(dq + 3) * ROWP + c] = __float2bfloat16(vv.w - __bfloat162float(h));
        }
        // ---- issue next tile's loads NOW; latency hidden behind MMA phase
        if (jt + 1 < ntiles) ldg_tile(j0 + 64, 960 - i0 + j0 + 64);
        __syncthreads();

        // ---- G half0 = Qr @ bandA^T
        {
            float gacc[4][4];
#pragma unroll
            for (int nf = 0; nf < 4; nf++)
#pragma unroll
                for (int i = 0; i < 4; i++) gacc[nf][i] = 0.f;
            mma_blk72(gacc, qr_h, qr_l, mrow, bA_h, bA_l, ncol, lane);
#pragma unroll
            for (int nf = 0; nf < 4; nf++) {
                int col = ncol + nf * 8 + tg * 2;
                G[r0 * GSTR + col]     = gacc[nf][0];
                G[r0 * GSTR + col + 1] = gacc[nf][1];
                G[r1 * GSTR + col]     = gacc[nf][2];
                G[r1 * GSTR + col + 1] = gacc[nf][3];
            }
        }

        // ---- AC = Qw @ K^T
        float sacc[4][4];
#pragma unroll
        for (int nf = 0; nf < 4; nf++)
#pragma unroll
            for (int i = 0; i < 4; i++) sacc[nf][i] = 0.f;
        mma_blk72(sacc, qw_h, qw_l, mrow, kk_h, kk_l, ncol, lane);

        // ---- G half1 = Qr @ bandB^T
        {
            float gacc[4][4];
#pragma unroll
            for (int nf = 0; nf < 4; nf++)
#pragma unroll
                for (int i = 0; i < 4; i++) gacc[nf][i] = 0.f;
            mma_blk72(gacc, qr_h, qr_l, mrow, bB_h, bB_l, ncol, lane);
#pragma unroll
            for (int nf = 0; nf < 4; nf++) {
                int col = 64 + ncol + nf * 8 + tg * 2;
                G[r0 * GSTR + col]     = gacc[nf][0];
                G[r0 * GSTR + col + 1] = gacc[nf][1];
                G[r1 * GSTR + col]     = gacc[nf][2];
                G[r1 * GSTR + col + 1] = gacc[nf][3];
            }
        }
        __syncthreads();   // G complete

        // ---- s = (AC + G[r][63-r+c])*scale, causal mask, row max
        float rmax0 = -3.0e38f, rmax1 = -3.0e38f;
#pragma unroll
        for (int nf = 0; nf < 4; nf++) {
            int col = ncol + nf * 8 + tg * 2;
            float s00 = (sacc[nf][0] + G[r0 * GSTR + 63 - r0 + col])     * scale;
            float s01 = (sacc[nf][1] + G[r0 * GSTR + 63 - r0 + col + 1]) * scale;
            float s10 = (sacc[nf][2] + G[r1 * GSTR + 63 - r1 + col])     * scale;
            float s11 = (sacc[nf][3] + G[r1 * GSTR + 63 - r1 + col + 1]) * scale;
            int ir0 = i0 + r0, ir1 = i0 + r1;
            int jc = j0 + col;
            s00 = (jc     <= ir0) ? s00 : -1.0e30f;
            s01 = (jc + 1 <= ir0) ? s01 : -1.0e30f;
            s10 = (jc     <= ir1) ? s10 : -1.0e30f;
            s11 = (jc + 1 <= ir1) ? s11 : -1.0e30f;
            sacc[nf][0] = s00; sacc[nf][1] = s01;
            sacc[nf][2] = s10; sacc[nf][3] = s11;
            rmax0 = fmaxf(rmax0, fmaxf(s00, s01));
            rmax1 = fmaxf(rmax1, fmaxf(s10, s11));
        }
        rmax0 = fmaxf(rmax0, __shfl_xor_sync(0xffffffffu, rmax0, 1));
        rmax0 = fmaxf(rmax0, __shfl_xor_sync(0xffffffffu, rmax0, 2));
        rmax1 = fmaxf(rmax1, __shfl_xor_sync(0xffffffffu, rmax1, 1));
        rmax1 = fmaxf(rmax1, __shfl_xor_sync(0xffffffffu, rmax1, 2));
        if (tg == 0) { pmax[wn * 64 + r0] = rmax0; pmax[wn * 64 + r1] = rmax1; }
        __syncthreads();

        // ---- exp + P write (aliases G; all G reads done above)
        float nm0 = fmaxf(m_s[r0], fmaxf(pmax[r0], pmax[64 + r0]));
        float nm1 = fmaxf(m_s[r1], fmaxf(pmax[r1], pmax[64 + r1]));
        float rs0 = 0.f, rs1 = 0.f;
#pragma unroll
        for (int nf = 0; nf < 4; nf++) {
            int col = ncol + nf * 8 + tg * 2;
            float p00 = __expf(sacc[nf][0] - nm0);
            float p01 = __expf(sacc[nf][1] - nm0);
            float p10 = __expf(sacc[nf][2] - nm1);
            float p11 = __expf(sacc[nf][3] - nm1);
            rs0 += p00 + p01; rs1 += p10 + p11;
            __nv_bfloat16 h00 = __float2bfloat16(p00);
            __nv_bfloat16 h01 = __float2bfloat16(p01);
            __nv_bfloat16 h10 = __float2bfloat16(p10);
            __nv_bfloat16 h11 = __float2bfloat16(p11);
            *(unsigned*)&pp_h[r0 * ROWP + col] = pack_bf2(h00, h01);
            *(unsigned*)&pp_h[r1 * ROWP + col] = pack_bf2(h10, h11);
            *(unsigned*)&pp_l[r0 * ROWP + col] = pack_bf2(
                __float2bfloat16(p00 - __bfloat162float(h00)),
                __float2bfloat16(p01 - __bfloat162float(h01)));
            *(unsigned*)&pp_l[r1 * ROWP + col] = pack_bf2(
                __float2bfloat16(p10 - __bfloat162float(h10)),
                __float2bfloat16(p11 - __bfloat162float(h11)));
        }
        rs0 += __shfl_xor_sync(0xffffffffu, rs0, 1);
        rs0 += __shfl_xor_sync(0xffffffffu, rs0, 2);
        rs1 += __shfl_xor_sync(0xffffffffu, rs1, 1);
        rs1 += __shfl_xor_sync(0xffffffffu, rs1, 2);
        if (tg == 0) { psum[wn * 64 + r0] = rs0; psum[wn * 64 + r1] = rs1; }
        __syncthreads();

        // ---- flash state update
        if (tid < 64) {
            float mo = m_s[tid];
            float nm = fmaxf(mo, fmaxf(pmax[tid], pmax[64 + tid]));
            float co = __expf(mo - nm);
            corr_s[tid] = co;
            l_s[tid] = l_s[tid] * co + psum[tid] + psum[64 + tid];
            m_s[tid] = nm;
        }
        __syncthreads();

        // ---- PV: acc = acc*corr + P @ V^T
        float c0 = corr_s[r0], c1 = corr_s[r1];
#pragma unroll
        for (int nf = 0; nf < 4; nf++) {
            acc[nf][0] *= c0; acc[nf][1] *= c0;
            acc[nf][2] *= c1; acc[nf][3] *= c1;
        }
        mma_blk72(acc, pp_h, pp_l, mrow, vt_h, vt_l, ncol, lane);

        // ---- rotate band buffers: this half1 becomes next half0
        __nv_bfloat16* t;
        t = bA_h; bA_h = bB_h; bB_h = t;
        t = bA_l; bA_l = bB_l; bB_l = t;
    }

    float inv0 = 1.0f / l_s[r0];
    float inv1 = 1.0f / l_s[r1];
#pragma unroll
    for (int nf = 0; nf < 4; nf++) {
        int col = ncol + nf * 8 + tg * 2;
        size_t o0 = (size_t)((i0 + r0) * BSZ + b) * HD + n * 64 + col;
        size_t o1 = (size_t)((i0 + r1) * BSZ + b) * HD + n * 64 + col;
        *(float2*)&vec[o0] = make_float2(acc[nf][0] * inv0, acc[nf][1] * inv0);
        *(float2*)&vec[o1] = make_float2(acc[nf][2] * inv1, acc[nf][3] * inv1);
    }
}

// ---------------- residual + LayerNorm -------------------------------------
__global__ __launch_bounds__(256) void ln_kernel(
    const float* __restrict__ w, const float* __restrict__ ao,
    const float* __restrict__ gamma, const float* __restrict__ beta,
    float* __restrict__ out)
{
    int row = blockIdx.x;
    const float* wr = w  + (size_t)row * DM;
    const float* ar = ao + (size_t)row * DM;
    int tid = threadIdx.x;

    float x[4];
    float sum = 0.f, ssq = 0.f;
#pragma unroll
    for (int k = 0; k < 4; k++) {
        int d = tid + k * 256;
        x[k] = wr[d] + ar[d];
        sum += x[k];
        ssq += x[k] * x[k];
    }
#pragma unroll
    for (int o = 16; o > 0; o >>= 1) {
        sum += __shfl_xor_sync(0xffffffffu, sum, o);
        ssq += __shfl_xor_sync(0xffffffffu, ssq, o);
    }
    __shared__ float reds[8], redq[8];
    __shared__ float mu_s, rstd_s;
    int wid = tid >> 5, lane = tid & 31;
    if (lane == 0) { reds[wid] = sum; redq[wid] = ssq; }
    __syncthreads();
    if (tid == 0) {
        float s = 0.f, q = 0.f;
#pragma unroll
        for (int i = 0; i < 8; i++) { s += reds[i]; q += redq[i]; }
        float mu = s * (1.0f / DM);
        float var = q * (1.0f / DM) - mu * mu;
        mu_s = mu;
        rstd_s = rsqrtf(var + 1e-5f);
    }
    __syncthreads();
    float mu = mu_s, rstd = rstd_s;
#pragma unroll
    for (int k = 0; k < 4; k++) {
        int d = tid + k * 256;
        out[(size_t)row * DM + d] = (x[k] - mu) * rstd * gamma[d] + beta[d];
    }
}

// ---------------- launch ----------------------------------------------------
extern "C" void kernel_launch(void* const* d_in, const int* in_sizes, int n_in,
                              void* d_out, int out_size)
{
    const float* w    = (const float*)d_in[0];
    const float* r    = (const float*)d_in[1];
    const float* rwb  = (const float*)d_in[2];
    const float* rrb  = (const float*)d_in[3];
    // d_in[4] = attn_mask: deterministic causal tril -> applied analytically
    const float* Wqkv = (const float*)d_in[5];
    const float* Wr   = (const float*)d_in[6];
    const float* Wo   = (const float*)d_in[7];
    const float* gam  = (const float*)d_in[8];
    const float* bet  = (const float*)d_in[9];
    float* out = (float*)d_out;

    float *heads, *rkp, *vecp, *aop;
    cudaGetSymbolAddress((void**)&heads, g_heads);
    cudaGetSymbolAddress((void**)&rkp,   g_rk);
    cudaGetSymbolAddress((void**)&vecp,  g_vec);
    cudaGetSymbolAddress((void**)&aop,   g_ao);

    cudaFuncSetAttribute(gemm_mma, cudaFuncAttributeMaxDynamicSharedMemorySize,
                         GEMM_SMEM);
    cudaFuncSetAttribute(attn_mma, cudaFuncAttributeMaxDynamicSharedMemorySize,
                         ATTN_SMEM);

    // 1) heads = w @ W_qkv
    gemm_mma<<<dim3(3072 / 128, 4096 / 128), 256, GEMM_SMEM>>>(
        w, Wqkv, heads, ROWS, 3 * HD, DM);
    // 2) r_k = r @ W_r
    gemm_mma<<<dim3(HD / 128, QLEN / 128), 256, GEMM_SMEM>>>(
        r, Wr, rkp, QLEN, HD, DM);

    // 3) fused relative attention
    attn_mma<<<dim3(QLEN / 64, NH, BSZ), 256, ATTN_SMEM>>>(heads, rkp, rwb, rrb, vecp);

    // 4) attn_out = vec @ W_o
    gemm_mma<<<dim3(DM / 128, ROWS / 128), 256, GEMM_SMEM>>>(
        vecp, Wo, aop, ROWS, DM, HD);

    // 5) residual + layernorm
    ln_kernel<<<ROWS, 256>>>(w, aop, gam, bet, out);
}

// round 13
// speedup vs baseline: 1.8121x; 1.0204x over previous
#include <cuda_runtime.h>
#include <cuda_bf16.h>
#include <math.h>

#define QLEN 1024
#define BSZ 4
#define DM 1024
#define NH 16
#define DH 64
#define HD (NH*DH)          /* 1024 */
#define ROWS (QLEN*BSZ)     /* 4096 */

// ---------------- scratch (device globals; no allocation allowed) ----------
__device__ __align__(16) float g_heads[ROWS * 3 * HD];
__device__ __align__(16) float g_rk[QLEN * HD];
__device__ __align__(16) float g_vec[ROWS * HD];
__device__ __align__(16) float g_ao[ROWS * DM];

// ============================================================================
// helpers
// ============================================================================
__device__ __forceinline__ void mma16816(float* c, const unsigned* a, const unsigned* b)
{
    asm volatile(
        "mma.sync.aligned.m16n8k16.row.col.f32.bf16.bf16.f32 "
        "{%0,%1,%2,%3}, {%4,%5,%6,%7}, {%8,%9}, {%0,%1,%2,%3};\n"
        : "+f"(c[0]), "+f"(c[1]), "+f"(c[2]), "+f"(c[3])
        : "r"(a[0]), "r"(a[1]), "r"(a[2]), "r"(a[3]), "r"(b[0]), "r"(b[1]));
}

__device__ __forceinline__ unsigned pack_bf2(__nv_bfloat16 a, __nv_bfloat16 b)
{
    return ((unsigned)__bfloat16_as_ushort(b) << 16) | __bfloat16_as_ushort(a);
}

// split a float4 into hi (uint2) and lo (uint2) packed bf16 pairs
__device__ __forceinline__ void split4(float4 v, uint2& hv, uint2& lv)
{
    __nv_bfloat16 h0 = __float2bfloat16(v.x);
    __nv_bfloat16 h1 = __float2bfloat16(v.y);
    __nv_bfloat16 h2 = __float2bfloat16(v.z);
    __nv_bfloat16 h3 = __float2bfloat16(v.w);
    hv.x = pack_bf2(h0, h1);
    hv.y = pack_bf2(h2, h3);
    lv.x = pack_bf2(__float2bfloat16(v.x - __bfloat162float(h0)),
                    __float2bfloat16(v.y - __bfloat162float(h1)));
    lv.y = pack_bf2(__float2bfloat16(v.z - __bfloat162float(h2)),
                    __float2bfloat16(v.w - __bfloat162float(h3)));
}

__device__ __forceinline__ void ldsm4(unsigned* r, const __nv_bfloat16* p)
{
    unsigned a = (unsigned)__cvta_generic_to_shared(p);
    asm volatile("ldmatrix.sync.aligned.m8n8.x4.shared.b16 {%0,%1,%2,%3}, [%4];\n"
                 : "=r"(r[0]), "=r"(r[1]), "=r"(r[2]), "=r"(r[3]) : "r"(a));
}

// 3-term bf16-split MMA block for attention tiles (stride 72):
// acc[4][4] += A[arow..arow+15][0..63] @ B[brow..brow+31][0..63]^T
__device__ __forceinline__ void mma_blk72(
    float (&acc)[4][4],
    const __nv_bfloat16* Ah, const __nv_bfloat16* Al, int arow,
    const __nv_bfloat16* Bh, const __nv_bfloat16* Bl, int brow, int lane)
{
    const int a_r = arow + (lane & 7) + ((lane >> 3) & 1) * 8;
    const int a_c = ((lane >> 4) & 1) * 8;
    const int b_r = brow + (lane & 7) + ((lane >> 4) & 1) * 8;
    const int b_c = ((lane >> 3) & 1) * 8;
#pragma unroll
    for (int ks = 0; ks < 4; ks++) {
        int kb = ks * 16;
        unsigned ah[4], al[4], bh[2][4], bl[2][4];
        ldsm4(ah, &Ah[a_r * 72 + kb + a_c]);
        ldsm4(al, &Al[a_r * 72 + kb + a_c]);
        ldsm4(bh[0], &Bh[b_r * 72 + kb + b_c]);
        ldsm4(bh[1], &Bh[(b_r + 16) * 72 + kb + b_c]);
        ldsm4(bl[0], &Bl[b_r * 72 + kb + b_c]);
        ldsm4(bl[1], &Bl[(b_r + 16) * 72 + kb + b_c]);
#pragma unroll
        for (int p = 0; p < 2; p++) {
            mma16816(acc[2*p],     ah, &bh[p][0]);
            mma16816(acc[2*p],     ah, &bl[p][0]);
            mma16816(acc[2*p],     al, &bh[p][0]);
            mma16816(acc[2*p + 1], ah, &bh[p][2]);
            mma16816(acc[2*p + 1], ah, &bl[p][2]);
            mma16816(acc[2*p + 1], al, &bh[p][2]);
        }
    }
}

// ============================================================================
// Tensor-core GEMM: C[M,N] = A[M,K] @ B[K,N], fp32 in/out, bf16 hi/lo split.
// 128x128x32 tile, 512 threads (16 warps, warp-tile 32x32). Register prefetch
// + double-buffered smem + ldmatrix loads + STS.64 fills.
// ============================================================================
#define APAD 40
#define GTILE (128*APAD)
#define GEMM_SMEM (2 * 4 * GTILE * 2)   /* 81920 bytes */

__global__ __launch_bounds__(512) void gemm_mma(
    const float* __restrict__ A, const float* __restrict__ B,
    float* __restrict__ C, int M, int N, int K)
{
    extern __shared__ char smraw[];
    __nv_bfloat16* sm = (__nv_bfloat16*)smraw;

    const int tid  = threadIdx.x;
    const int row0 = blockIdx.y * 128;
    const int col0 = blockIdx.x * 128;
    const int warp = tid >> 5, lane = tid & 31;
    const int wm = warp & 3;        // m-block of 32 rows
    const int wn = warp >> 2;       // n-block of 32 cols
    const int g  = lane >> 2;
    const int tg = lane & 3;

    const int a_roff = (lane & 7) + ((lane >> 3) & 1) * 8;
    const int a_coff = ((lane >> 4) & 1) * 8;
    const int b_roff = (lane & 7) + ((lane >> 4) & 1) * 8;
    const int b_coff = ((lane >> 3) & 1) * 8;

    float acc[2][4][4];
#pragma unroll
    for (int mf = 0; mf < 2; mf++)
#pragma unroll
        for (int nf = 0; nf < 4; nf++)
#pragma unroll
            for (int i = 0; i < 4; i++) acc[mf][nf][i] = 0.f;

    float4 aV[2];     // A: 2 (row, k-quad) chunks
    float4 bV[2];     // B: 2 (n, k-quad) groups

    auto ldg = [&](int k0) {
#pragma unroll
        for (int i = 0; i < 2; i++) {
            int ch = tid + i * 512;      // 0..1023
            aV[i] = *(const float4*)&A[(size_t)(row0 + (ch >> 3)) * K
                                       + k0 + (ch & 7) * 4];
        }
#pragma unroll
        for (int i = 0; i < 2; i++) {
            int e = tid + i * 512;       // 0..1023
            int kq = e >> 7;             // 0..7 (k-quad)
            int nn = e & 127;
            bV[i].x = B[(size_t)(k0 + kq * 4 + 0) * N + col0 + nn];
            bV[i].y = B[(size_t)(k0 + kq * 4 + 1) * N + col0 + nn];
            bV[i].z = B[(size_t)(k0 + kq * 4 + 2) * N + col0 + nn];
            bV[i].w = B[(size_t)(k0 + kq * 4 + 3) * N + col0 + nn];
        }
    };

    auto sts = [&](int bsel) {
        __nv_bfloat16* sAh = sm + bsel * 4 * GTILE;
        __nv_bfloat16* sAl = sAh + GTILE;
        __nv_bfloat16* sBh = sAl + GTILE;
        __nv_bfloat16* sBl = sBh + GTILE;
#pragma unroll
        for (int i = 0; i < 2; i++) {
            int ch = tid + i * 512;
            int r = ch >> 3, kq = (ch & 7) * 4;
            uint2 hv, lv;
            split4(aV[i], hv, lv);
            *(uint2*)&sAh[r * APAD + kq] = hv;
            *(uint2*)&sAl[r * APAD + kq] = lv;
        }
#pragma unroll
        for (int i = 0; i < 2; i++) {
            int e = tid + i * 512;
            int kq = e >> 7;
            int nn = e & 127;
            uint2 hv, lv;
            split4(bV[i], hv, lv);
            *(uint2*)&sBh[nn * APAD + kq * 4] = hv;
            *(uint2*)&sBl[nn * APAD + kq * 4] = lv;
        }
    };

    const int nk = K / 32;
    ldg(0);

    for (int it = 0; it < nk; it++) {
        sts(it & 1);
        __syncthreads();
        if (it + 1 < nk) ldg((it + 1) * 32);

        const __nv_bfloat16* cAh = sm + (it & 1) * 4 * GTILE;
        const __nv_bfloat16* cAl = cAh + GTILE;
        const __nv_bfloat16* cBh = cAl + GTILE;
        const __nv_bfloat16* cBl = cBh + GTILE;

#pragma unroll
        for (int ks = 0; ks < 2; ks++) {
            int kb = ks * 16;
            unsigned bh[2][4], bl[2][4];
            ldsm4(bh[0], &cBh[(wn * 32 + b_roff) * APAD + kb + b_coff]);
            ldsm4(bh[1], &cBh[(wn * 32 + 16 + b_roff) * APAD + kb + b_coff]);
            ldsm4(bl[0], &cBl[(wn * 32 + b_roff) * APAD + kb + b_coff]);
            ldsm4(bl[1], &cBl[(wn * 32 + 16 + b_roff) * APAD + kb + b_coff]);
#pragma unroll
            for (int mf = 0; mf < 2; mf++) {
                const int ar = wm * 32 + mf * 16 + a_roff;
                unsigned ah[4], al[4];
                ldsm4(ah, &cAh[ar * APAD + kb + a_coff]);
                ldsm4(al, &cAl[ar * APAD + kb + a_coff]);
#pragma unroll
                for (int p = 0; p < 2; p++) {
                    mma16816(acc[mf][2*p],     ah, &bh[p][0]);
                    mma16816(acc[mf][2*p],     ah, &bl[p][0]);
                    mma16816(acc[mf][2*p],     al, &bh[p][0]);
                    mma16816(acc[mf][2*p + 1], ah, &bh[p][2]);
                    mma16816(acc[mf][2*p + 1], ah, &bl[p][2]);
                    mma16816(acc[mf][2*p + 1], al, &bh[p][2]);
                }
            }
        }
    }

#pragma unroll
    for (int mf = 0; mf < 2; mf++) {
        int r = row0 + wm * 32 + mf * 16 + g;
#pragma unroll
        for (int nf = 0; nf < 4; nf++) {
            int c = col0 + wn * 32 + nf * 8 + tg * 2;
            *(float2*)&C[(size_t)r * N + c]       = make_float2(acc[mf][nf][0], acc[mf][nf][1]);
            *(float2*)&C[(size_t)(r + 8) * N + c] = make_float2(acc[mf][nf][2], acc[mf][nf][3]);
        }
    }
}

// ============================================================================
// Tensor-core fused rel-attention (flash-style, bf16-split MMAs, ldmatrix,
// band rotation, float4 register-staged prefetch of K/V/band).
// Grid (QLEN/64, NH, BSZ), 256 threads (8 warps). UNCHANGED from R12 pass.
// ============================================================================
#define ROWP 72
#define TBYTES (64*ROWP*2)        /* 9216 bytes per bf16 tile */
#define OFF_UNION (12*TBYTES)     /* G (f32 64x133) aliases P hi/lo */
#define GSTR 133
#define OFF_MISC (OFF_UNION + 64*GSTR*4)
#define ATTN_SMEM (OFF_MISC + 3*256 + 2*512)

__global__ __launch_bounds__(256) void attn_mma(
    const float* __restrict__ heads, const float* __restrict__ rk,
    const float* __restrict__ rwb, const float* __restrict__ rrb,
    float* __restrict__ vec)
{
    extern __shared__ char smc[];
    __nv_bfloat16* qw_h = (__nv_bfloat16*)(smc);
    __nv_bfloat16* qw_l = (__nv_bfloat16*)(smc + 1*TBYTES);
    __nv_bfloat16* qr_h = (__nv_bfloat16*)(smc + 2*TBYTES);
    __nv_bfloat16* qr_l = (__nv_bfloat16*)(smc + 3*TBYTES);
    __nv_bfloat16* kk_h = (__nv_bfloat16*)(smc + 4*TBYTES);
    __nv_bfloat16* kk_l = (__nv_bfloat16*)(smc + 5*TBYTES);
    __nv_bfloat16* vt_h = (__nv_bfloat16*)(smc + 6*TBYTES);
    __nv_bfloat16* vt_l = (__nv_bfloat16*)(smc + 7*TBYTES);
    __nv_bfloat16* bA_h = (__nv_bfloat16*)(smc + 8*TBYTES);   // band half0
    __nv_bfloat16* bA_l = (__nv_bfloat16*)(smc + 9*TBYTES);
    __nv_bfloat16* bB_h = (__nv_bfloat16*)(smc + 10*TBYTES);  // band half1
    __nv_bfloat16* bB_l = (__nv_bfloat16*)(smc + 11*TBYTES);
    __nv_bfloat16* pp_h = (__nv_bfloat16*)(smc + OFF_UNION);
    __nv_bfloat16* pp_l = (__nv_bfloat16*)(smc + OFF_UNION + TBYTES);
    float* G      = (float*)(smc + OFF_UNION);   // aliases pp (disjoint in time)
    float* m_s    = (float*)(smc + OFF_MISC);
    float* l_s    = (float*)(smc + OFF_MISC + 256);
    float* corr_s = (float*)(smc + OFF_MISC + 512);
    float* pmax   = (float*)(smc + OFF_MISC + 768);
    float* psum   = (float*)(smc + OFF_MISC + 1280);

    const int tid = threadIdx.x;
    const int warp = tid >> 5, lane = tid & 31;
    const int g = lane >> 2, tg = lane & 3;
    const int mrow = (warp & 3) * 16;
    const int ncol = (warp >> 2) * 32;
    const int wn = warp >> 2;
    const int i0 = blockIdx.x * 64;
    const int n  = blockIdx.y;
    const int b  = blockIdx.z;
    const int r0 = mrow + g, r1 = r0 + 8;

    // ---- Q load + biases, hi/lo split
    for (int idx = tid; idx < 4096; idx += 256) {
        int r = idx >> 6, d = idx & 63;
        float v = heads[(size_t)((i0 + r) * BSZ + b) * 3072 + n * 64 + d];
        float vw = v + rwb[n * 64 + d];
        float vr = v + rrb[n * 64 + d];
        __nv_bfloat16 h = __float2bfloat16(vw);
        qw_h[r * ROWP + d] = h;
        qw_l[r * ROWP + d] = __float2bfloat16(vw - __bfloat162float(h));
        h = __float2bfloat16(vr);
        qr_h[r * ROWP + d] = h;
        qr_l[r * ROWP + d] = __float2bfloat16(vr - __bfloat162float(h));
    }
    if (tid < 64) { m_s[tid] = -3.0e38f; l_s[tid] = 0.f; }

    // ---- band half0 for jt=0 (rows base0..base0+63, all < QLEN) direct store
    {
        const int base0 = 960 - i0;
#pragma unroll
        for (int i = 0; i < 4; i++) {
            int ch = tid + i * 256;          // 0..1023
            int t = ch >> 4, dq = (ch & 15) * 4;
            float4 v = *(const float4*)&rk[(size_t)(base0 + t) * HD + n * 64 + dq];
            uint2 hv, lv;
            split4(v, hv, lv);
            *(uint2*)&bA_h[t * ROWP + dq] = hv;
            *(uint2*)&bA_l[t * ROWP + dq] = lv;
        }
    }

    float4 kV[4], vV[4], bV[4];   // register staging for next tile

    auto ldg_tile = [&](int j0, int base) {
#pragma unroll
        for (int i = 0; i < 4; i++) {
            int ch = tid + i * 256;
            int c = ch >> 4, dq = (ch & 15) * 4;
            size_t off = (size_t)((j0 + c) * BSZ + b) * 3072 + n * 64 + dq;
            kV[i] = *(const float4*)&heads[off + 1024];
            vV[i] = *(const float4*)&heads[off + 2048];
            int grow = base + 64 + c;
            if (grow < QLEN)
                bV[i] = *(const float4*)&rk[(size_t)grow * HD + n * 64 + dq];
            else
                bV[i] = make_float4(0.f, 0.f, 0.f, 0.f);
        }
    };

    float acc[4][4];
#pragma unroll
    for (int nf = 0; nf < 4; nf++)
#pragma unroll
        for (int i = 0; i < 4; i++) acc[nf][i] = 0.f;

    const float scale = 0.125f;
    const int ntiles = blockIdx.x + 1;

    ldg_tile(0, 960 - i0);   // prologue: stage jt=0 K/V/band-half1

    for (int jt = 0; jt < ntiles; ++jt) {
        const int j0 = jt * 64;
        __syncthreads();   // previous iter's smem reads complete

        // ---- STS staged K / V^T / band-half1 (fast: no LDG latency here)
#pragma unroll
        for (int i = 0; i < 4; i++) {
            int ch = tid + i * 256;
            int c = ch >> 4, dq = (ch & 15) * 4;
            uint2 hv, lv;
            split4(kV[i], hv, lv);
            *(uint2*)&kk_h[c * ROWP + dq] = hv;
            *(uint2*)&kk_l[c * ROWP + dq] = lv;
            split4(bV[i], hv, lv);
            *(uint2*)&bB_h[c * ROWP + dq] = hv;
            *(uint2*)&bB_l[c * ROWP + dq] = lv;
            // V transposed: scalar stores
            float4 vv = vV[i];
            __nv_bfloat16 h;
            h = __float2bfloat16(vv.x);
            vt_h[(dq + 0) * ROWP + c] = h;
            vt_l[(dq + 0) * ROWP + c] = __float2bfloat16(vv.x - __bfloat162float(h));
            h = __float2bfloat16(vv.y);
            vt_h[(dq + 1) * ROWP + c] = h;
            vt_l[(dq + 1) * ROWP + c] = __float2bfloat16(vv.y - __bfloat162float(h));
            h = __float2bfloat16(vv.z);
            vt_h[(dq + 2) * ROWP + c] = h;
            vt_l[(dq + 2) * ROWP + c] = __float2bfloat16(vv.z - __bfloat162float(h));
            h = __float2bfloat16(vv.w);
            vt_h[(dq + 3) * ROWP + c] = h;
            vt_l[(dq + 3) * ROWP + c] = __float2bfloat16(vv.w - __bfloat162float(h));
        }
        // ---- issue next tile's loads NOW; latency hidden behind MMA phase
        if (jt + 1 < ntiles) ldg_tile(j0 + 64, 960 - i0 + j0 + 64);
        __syncthreads();

        // ---- G half0 = Qr @ bandA^T
        {
            float gacc[4][4];
#pragma unroll
            for (int nf = 0; nf < 4; nf++)
#pragma unroll
                for (int i = 0; i < 4; i++) gacc[nf][i] = 0.f;
            mma_blk72(gacc, qr_h, qr_l, mrow, bA_h, bA_l, ncol, lane);
#pragma unroll
            for (int nf = 0; nf < 4; nf++) {
                int col = ncol + nf * 8 + tg * 2;
                G[r0 * GSTR + col]     = gacc[nf][0];
                G[r0 * GSTR + col + 1] = gacc[nf][1];
                G[r1 * GSTR + col]     = gacc[nf][2];
                G[r1 * GSTR + col + 1] = gacc[nf][3];
            }
        }

        // ---- AC = Qw @ K^T
        float sacc[4][4];
#pragma unroll
        for (int nf = 0; nf < 4; nf++)
#pragma unroll
            for (int i = 0; i < 4; i++) sacc[nf][i] = 0.f;
        mma_blk72(sacc, qw_h, qw_l, mrow, kk_h, kk_l, ncol, lane);

        // ---- G half1 = Qr @ bandB^T
        {
            float gacc[4][4];
#pragma unroll
            for (int nf = 0; nf < 4; nf++)
#pragma unroll
                for (int i = 0; i < 4; i++) gacc[nf][i] = 0.f;
            mma_blk72(gacc, qr_h, qr_l, mrow, bB_h, bB_l, ncol, lane);
#pragma unroll
            for (int nf = 0; nf < 4; nf++) {
                int col = 64 + ncol + nf * 8 + tg * 2;
                G[r0 * GSTR + col]     = gacc[nf][0];
                G[r0 * GSTR + col + 1] = gacc[nf][1];
                G[r1 * GSTR + col]     = gacc[nf][2];
                G[r1 * GSTR + col + 1] = gacc[nf][3];
            }
        }
        __syncthreads();   // G complete

        // ---- s = (AC + G[r][63-r+c])*scale, causal mask, row max
        float rmax0 = -3.0e38f, rmax1 = -3.0e38f;
#pragma unroll
        for (int nf = 0; nf < 4; nf++) {
            int col = ncol + nf * 8 + tg * 2;
            float s00 = (sacc[nf][0] + G[r0 * GSTR + 63 - r0 + col])     * scale;
            float s01 = (sacc[nf][1] + G[r0 * GSTR + 63 - r0 + col + 1]) * scale;
            float s10 = (sacc[nf][2] + G[r1 * GSTR + 63 - r1 + col])     * scale;
            float s11 = (sacc[nf][3] + G[r1 * GSTR + 63 - r1 + col + 1]) * scale;
            int ir0 = i0 + r0, ir1 = i0 + r1;
            int jc = j0 + col;
            s00 = (jc     <= ir0) ? s00 : -1.0e30f;
            s01 = (jc + 1 <= ir0) ? s01 : -1.0e30f;
            s10 = (jc     <= ir1) ? s10 : -1.0e30f;
            s11 = (jc + 1 <= ir1) ? s11 : -1.0e30f;
            sacc[nf][0] = s00; sacc[nf][1] = s01;
            sacc[nf][2] = s10; sacc[nf][3] = s11;
            rmax0 = fmaxf(rmax0, fmaxf(s00, s01));
            rmax1 = fmaxf(rmax1, fmaxf(s10, s11));
        }
        rmax0 = fmaxf(rmax0, __shfl_xor_sync(0xffffffffu, rmax0, 1));
        rmax0 = fmaxf(rmax0, __shfl_xor_sync(0xffffffffu, rmax0, 2));
        rmax1 = fmaxf(rmax1, __shfl_xor_sync(0xffffffffu, rmax1, 1));
        rmax1 = fmaxf(rmax1, __shfl_xor_sync(0xffffffffu, rmax1, 2));
        if (tg == 0) { pmax[wn * 64 + r0] = rmax0; pmax[wn * 64 + r1] = rmax1; }
        __syncthreads();

        // ---- exp + P write (aliases G; all G reads done above)
        float nm0 = fmaxf(m_s[r0], fmaxf(pmax[r0], pmax[64 + r0]));
        float nm1 = fmaxf(m_s[r1], fmaxf(pmax[r1], pmax[64 + r1]));
        float rs0 = 0.f, rs1 = 0.f;
#pragma unroll
        for (int nf = 0; nf < 4; nf++) {
            int col = ncol + nf * 8 + tg * 2;
            float p00 = __expf(sacc[nf][0] - nm0);
            float p01 = __expf(sacc[nf][1] - nm0);
            float p10 = __expf(sacc[nf][2] - nm1);
            float p11 = __expf(sacc[nf][3] - nm1);
            rs0 += p00 + p01; rs1 += p10 + p11;
            __nv_bfloat16 h00 = __float2bfloat16(p00);
            __nv_bfloat16 h01 = __float2bfloat16(p01);
            __nv_bfloat16 h10 = __float2bfloat16(p10);
            __nv_bfloat16 h11 = __float2bfloat16(p11);
            *(unsigned*)&pp_h[r0 * ROWP + col] = pack_bf2(h00, h01);
            *(unsigned*)&pp_h[r1 * ROWP + col] = pack_bf2(h10, h11);
            *(unsigned*)&pp_l[r0 * ROWP + col] = pack_bf2(
                __float2bfloat16(p00 - __bfloat162float(h00)),
                __float2bfloat16(p01 - __bfloat162float(h01)));
            *(unsigned*)&pp_l[r1 * ROWP + col] = pack_bf2(
                __float2bfloat16(p10 - __bfloat162float(h10)),
                __float2bfloat16(p11 - __bfloat162float(h11)));
        }
        rs0 += __shfl_xor_sync(0xffffffffu, rs0, 1);
        rs0 += __shfl_xor_sync(0xffffffffu, rs0, 2);
        rs1 += __shfl_xor_sync(0xffffffffu, rs1, 1);
        rs1 += __shfl_xor_sync(0xffffffffu, rs1, 2);
        if (tg == 0) { psum[wn * 64 + r0] = rs0; psum[wn * 64 + r1] = rs1; }
        __syncthreads();

        // ---- flash state update
        if (tid < 64) {
            float mo = m_s[tid];
            float nm = fmaxf(mo, fmaxf(pmax[tid], pmax[64 + tid]));
            float co = __expf(mo - nm);
            corr_s[tid] = co;
            l_s[tid] = l_s[tid] * co + psum[tid] + psum[64 + tid];
            m_s[tid] = nm;
        }
        __syncthreads();

        // ---- PV: acc = acc*corr + P @ V^T
        float c0 = corr_s[r0], c1 = corr_s[r1];
#pragma unroll
        for (int nf = 0; nf < 4; nf++) {
            acc[nf][0] *= c0; acc[nf][1] *= c0;
            acc[nf][2] *= c1; acc[nf][3] *= c1;
        }
        mma_blk72(acc, pp_h, pp_l, mrow, vt_h, vt_l, ncol, lane);

        // ---- rotate band buffers: this half1 becomes next half0
        __nv_bfloat16* t;
        t = bA_h; bA_h = bB_h; bB_h = t;
        t = bA_l; bA_l = bB_l; bB_l = t;
    }

    float inv0 = 1.0f / l_s[r0];
    float inv1 = 1.0f / l_s[r1];
#pragma unroll
    for (int nf = 0; nf < 4; nf++) {
        int col = ncol + nf * 8 + tg * 2;
        size_t o0 = (size_t)((i0 + r0) * BSZ + b) * HD + n * 64 + col;
        size_t o1 = (size_t)((i0 + r1) * BSZ + b) * HD + n * 64 + col;
        *(float2*)&vec[o0] = make_float2(acc[nf][0] * inv0, acc[nf][1] * inv0);
        *(float2*)&vec[o1] = make_float2(acc[nf][2] * inv1, acc[nf][3] * inv1);
    }
}

// ---------------- residual + LayerNorm -------------------------------------
__global__ __launch_bounds__(256) void ln_kernel(
    const float* __restrict__ w, const float* __restrict__ ao,
    const float* __restrict__ gamma, const float* __restrict__ beta,
    float* __restrict__ out)
{
    int row = blockIdx.x;
    const float* wr = w  + (size_t)row * DM;
    const float* ar = ao + (size_t)row * DM;
    int tid = threadIdx.x;

    float x[4];
    float sum = 0.f, ssq = 0.f;
#pragma unroll
    for (int k = 0; k < 4; k++) {
        int d = tid + k * 256;
        x[k] = wr[d] + ar[d];
        sum += x[k];
        ssq += x[k] * x[k];
    }
#pragma unroll
    for (int o = 16; o > 0; o >>= 1) {
        sum += __shfl_xor_sync(0xffffffffu, sum, o);
        ssq += __shfl_xor_sync(0xffffffffu, ssq, o);
    }
    __shared__ float reds[8], redq[8];
    __shared__ float mu_s, rstd_s;
    int wid = tid >> 5, lane = tid & 31;
    if (lane == 0) { reds[wid] = sum; redq[wid] = ssq; }
    __syncthreads();
    if (tid == 0) {
        float s = 0.f, q = 0.f;
#pragma unroll
        for (int i = 0; i < 8; i++) { s += reds[i]; q += redq[i]; }
        float mu = s * (1.0f / DM);
        float var = q * (1.0f / DM) - mu * mu;
        mu_s = mu;
        rstd_s = rsqrtf(var + 1e-5f);
    }
    __syncthreads();
    float mu = mu_s, rstd = rstd_s;
#pragma unroll
    for (int k = 0; k < 4; k++) {
        int d = tid + k * 256;
        out[(size_t)row * DM + d] = (x[k] - mu) * rstd * gamma[d] + beta[d];
    }
}

// ---------------- launch ----------------------------------------------------
extern "C" void kernel_launch(void* const* d_in, const int* in_sizes, int n_in,
                              void* d_out, int out_size)
{
    const float* w    = (const float*)d_in[0];
    const float* r    = (const float*)d_in[1];
    const float* rwb  = (const float*)d_in[2];
    const float* rrb  = (const float*)d_in[3];
    // d_in[4] = attn_mask: deterministic causal tril -> applied analytically
    const float* Wqkv = (const float*)d_in[5];
    const float* Wr   = (const float*)d_in[6];
    const float* Wo   = (const float*)d_in[7];
    const float* gam  = (const float*)d_in[8];
    const float* bet  = (const float*)d_in[9];
    float* out = (float*)d_out;

    float *heads, *rkp, *vecp, *aop;
    cudaGetSymbolAddress((void**)&heads, g_heads);
    cudaGetSymbolAddress((void**)&rkp,   g_rk);
    cudaGetSymbolAddress((void**)&vecp,  g_vec);
    cudaGetSymbolAddress((void**)&aop,   g_ao);

    cudaFuncSetAttribute(gemm_mma, cudaFuncAttributeMaxDynamicSharedMemorySize,
                         GEMM_SMEM);
    cudaFuncSetAttribute(attn_mma, cudaFuncAttributeMaxDynamicSharedMemorySize,
                         ATTN_SMEM);

    // 1) heads = w @ W_qkv
    gemm_mma<<<dim3(3072 / 128, 4096 / 128), 512, GEMM_SMEM>>>(
        w, Wqkv, heads, ROWS, 3 * HD, DM);
    // 2) r_k = r @ W_r
    gemm_mma<<<dim3(HD / 128, QLEN / 128), 512, GEMM_SMEM>>>(
        r, Wr, rkp, QLEN, HD, DM);

    // 3) fused relative attention
    attn_mma<<<dim3(QLEN / 64, NH, BSZ), 256, ATTN_SMEM>>>(heads, rkp, rwb, rrb, vecp);

    // 4) attn_out = vec @ W_o
    gemm_mma<<<dim3(DM / 128, ROWS / 128), 512, GEMM_SMEM>>>(
        vecp, Wo, aop, ROWS, DM, HD);

    // 5) residual + layernorm
    ln_kernel<<<ROWS, 256>>>(w, aop, gam, bet, out);
}